// round 10
// baseline (speedup 1.0000x reference)
#include <cuda_runtime.h>
#include <cuda_bf16.h>
#include <math.h>

#define BB 4
#define TT 192
#define LL 120
#define GG 500
#define HH 500      // HL
#define H4 2000
#define H4P 2048
#define KPAD 520    // padded K (bf16 units); 1040B row stride -> LDSM conflict-free
#define NR 480
#define NRP 512
#define OD 24
#define M1 3000
#define M2 1000

// tiling: 128 blocks = 16 col-tiles(128 gate-cols) x 8 row-tiles(64 rows)
#define GRIDL 128
#define LSW (128 * KPAD * 2)    // 133120 W stripe bytes (resident)
#define LSA (64 * KPAD * 2)     // 66560 h stripe bytes
#define SMEML (LSW + LSA + 16)

#define GXW (128 * KPAD * 2)    // 133120 W_ih stripe (resident)
#define GXA (32 * KPAD * 2)     // 33280 H2 half-stripe
#define SMEMG (GXW + 2 * GXA + 32)

// ------------------------- scratch (device globals) -------------------------
__device__ float g_P[KPAD];
__device__ float g_Nv[KPAD];
__device__ __align__(16) float g_bias[H4P];                    // interleaved hc*4+gate
__device__ __align__(16) unsigned short g_WIHh[H4P * KPAD];    // bf16 W_ih [cq][f]
__device__ __align__(16) unsigned short g_Whh[H4P * KPAD];     // bf16 W_hh [cq][k]
__device__ __align__(16) unsigned short g_h2[(size_t)TT * NRP * KPAD];  // bf16 H2 [t][row][f]
__device__ __align__(16) float g_gt[(size_t)TT * GRIDL * 8 * 1024];     // gates fragments
__device__ __align__(16) unsigned short g_h3[3][NRP * KPAD];   // bf16 h ring [row][k]
__device__ __align__(16) float g_c[HH * NRP];                  // c fp32 [hc][row]
__device__ __align__(16) float g_hF[HH * NRP];                 // fp32 h_last [hc][row]
__device__ unsigned g_bar[TT];
__device__ __align__(16) float g_hT[NR * HH];
__device__ __align__(16) float g_z1[NR * M1];
__device__ __align__(16) float g_z2[NR * M2];
__device__ __align__(16) float g_z3[NR * M1];

// ------------------------- helpers -------------------------
__device__ __forceinline__ float fsig(float x) {
    return __fdividef(1.f, 1.f + __expf(-x));
}
__device__ __forceinline__ float ftanh(float x) {
    float ax = fabsf(x);
    float t  = __expf(-2.f * ax);
    float r  = __fdividef(1.f - t, 1.f + t);
    return copysignf(r, x);
}
__device__ __forceinline__ float tf32r(float x) {
    unsigned r;
    asm("cvt.rna.tf32.f32 %0, %1;" : "=r"(r) : "f"(x));
    return __uint_as_float(r);
}
__device__ __forceinline__ unsigned short f2bf(float v) {
    __nv_bfloat16 b = __float2bfloat16_rn(v);
    return *reinterpret_cast<unsigned short*>(&b);
}
__device__ __forceinline__ void mbar_init(unsigned a, unsigned c) {
    asm volatile("mbarrier.init.shared.b64 [%0], %1;" :: "r"(a), "r"(c) : "memory");
}
__device__ __forceinline__ void mbar_extx(unsigned a, unsigned tx) {
    asm volatile("mbarrier.arrive.expect_tx.shared.b64 _, [%0], %1;" :: "r"(a), "r"(tx) : "memory");
}
__device__ __forceinline__ void mbar_wait(unsigned a, unsigned ph) {
    asm volatile(
        "{\n\t.reg .pred P;\n"
        "W%=:\n\t"
        "mbarrier.try_wait.parity.acquire.cta.shared::cta.b64 P, [%0], %1, 0x989680;\n\t"
        "@P bra D%=;\n\t"
        "bra W%=;\n"
        "D%=:\n\t}"
        :: "r"(a), "r"(ph) : "memory");
}
__device__ __forceinline__ void bulkcp(unsigned dst, const void* src, unsigned bytes, unsigned mbar) {
    asm volatile(
        "cp.async.bulk.shared::cta.global.mbarrier::complete_tx::bytes [%0], [%1], %2, [%3];"
        :: "r"(dst), "l"(src), "r"(bytes), "r"(mbar) : "memory");
}
__device__ __forceinline__ void ldsm4(unsigned* r, unsigned addr) {
    asm volatile("ldmatrix.sync.aligned.m8n8.x4.shared.b16 {%0,%1,%2,%3}, [%4];"
                 : "=r"(r[0]), "=r"(r[1]), "=r"(r[2]), "=r"(r[3]) : "r"(addr));
}
__device__ __forceinline__ void mma16bf(float* d, const unsigned* a, const unsigned* b) {
    asm volatile(
        "mma.sync.aligned.m16n8k16.row.col.f32.bf16.bf16.f32 "
        "{%0,%1,%2,%3}, {%4,%5,%6,%7}, {%8,%9}, {%0,%1,%2,%3};"
        : "+f"(d[0]), "+f"(d[1]), "+f"(d[2]), "+f"(d[3])
        : "r"(a[0]), "r"(a[1]), "r"(a[2]), "r"(a[3]), "r"(b[0]), "r"(b[1]));
}
__device__ __forceinline__ void mma8(float* d, const unsigned* a, const unsigned* b) {
    asm volatile(
        "mma.sync.aligned.m16n8k8.row.col.f32.tf32.tf32.f32 "
        "{%0,%1,%2,%3}, {%4,%5,%6,%7}, {%8,%9}, {%0,%1,%2,%3};"
        : "+f"(d[0]), "+f"(d[1]), "+f"(d[2]), "+f"(d[3])
        : "r"(a[0]), "r"(a[1]), "r"(a[2]), "r"(a[3]), "r"(b[0]), "r"(b[1]));
}

// ------------------------- launch 1: P,N vectors -------------------------
__global__ void k_pn(const float* __restrict__ W1, const float* __restrict__ W2) {
    for (int f = threadIdx.x; f < KPAD; f += 512) {
        float p = 0.f, n = 0.f;
        if (f < GG) {
            for (int g = 0; g < GG; g++) {
                float w = W1[g];
                float v = W2[g * GG + f];
                p = fmaf(fmaxf(w, 0.f), v, p);
                n = fmaf(fmaxf(-w, 0.f), v, n);
            }
        }
        g_P[f]  = p;
        g_Nv[f] = n;
    }
}

// ------------------------- launch 2: weights -> bf16, row-permuted ----------
__global__ void k_wcvt(const float* __restrict__ W_ih, const float* __restrict__ W_hh,
                       const float* __restrict__ b_ih, const float* __restrict__ b_hh) {
    int h = blockIdx.x;
    int cq = (h % HH) * 4 + h / HH;
    const float* src = blockIdx.y ? (W_hh + (size_t)h * HH) : (W_ih + (size_t)h * GG);
    unsigned short* dst = (blockIdx.y ? g_Whh : g_WIHh) + (size_t)cq * KPAD;
    for (int f = threadIdx.x; f < KPAD; f += 256)
        dst[f] = (f < GG) ? f2bf(src[f]) : (unsigned short)0;
    if (blockIdx.y == 0 && threadIdx.x == 0)
        g_bias[cq] = b_ih[h] + b_hh[h];
}

// ------------------------- launch 3: GCN front -> H2 bf16 -------------------
__global__ void k_front(const float* __restrict__ x, const float* __restrict__ Ahat) {
    __shared__ float xr[LL], sp[LL], sn[LL], su[LL], sv[LL];
    __shared__ float sP[KPAD], sN[KPAD];
    int bid = blockIdx.x;
    int b = bid / TT, t = bid % TT;
    int tid = threadIdx.x;
    for (int f = tid; f < KPAD; f += 256) { sP[f] = g_P[f]; sN[f] = g_Nv[f]; }
    if (tid < LL) xr[tid] = x[(b * TT + t) * LL + tid];
    __syncthreads();
    if (tid < LL) {
        float s = 0.f;
        const float* Ar = &Ahat[tid * LL];
        for (int l = 0; l < LL; l++) s = fmaf(Ar[l], xr[l], s);
        sp[tid] = fmaxf(s, 0.f);
        sn[tid] = fmaxf(-s, 0.f);
    }
    __syncthreads();
    if (tid < LL) {
        float uu = 0.f, vv = 0.f;
        const float* Ar = &Ahat[tid * LL];
        for (int l = 0; l < LL; l++) {
            uu = fmaf(Ar[l], sp[l], uu);
            vv = fmaf(Ar[l], sn[l], vv);
        }
        su[tid] = uu;
        sv[tid] = vv;
    }
    __syncthreads();
    unsigned* dst = reinterpret_cast<unsigned*>(g_h2);
    for (int e = tid; e < LL * (KPAD / 2); e += 256) {
        int l = e / (KPAD / 2);
        int f2 = (e % (KPAD / 2)) * 2;
        float uu = su[l], vv = sv[l];
        float h0 = fmaxf(fmaf(uu, sP[f2],     vv * sN[f2]),     0.f);
        float h1 = fmaxf(fmaf(uu, sP[f2 + 1], vv * sN[f2 + 1]), 0.f);
        unsigned val = ((unsigned)f2bf(h1) << 16) | (unsigned)f2bf(h0);
        size_t row = (size_t)t * NRP + b * LL + l;
        dst[row * (KPAD / 2) + f2 / 2] = val;
    }
}

// ------------------------- launch 4: zero init -------------------------
__global__ void k_zero() {
    const size_t H3W  = 3ull * NRP * KPAD / 2;
    const size_t CW   = (size_t)HH * NRP;
    const size_t BARW = TT;
    const size_t PADW = (size_t)TT * (NRP - NR) * (KPAD / 2);
    const size_t TOTAL = H3W + CW + BARW + PADW;
    size_t stride = (size_t)gridDim.x * 256;
    for (size_t i = (size_t)blockIdx.x * 256 + threadIdx.x; i < TOTAL; i += stride) {
        if (i < H3W) {
            reinterpret_cast<unsigned*>(g_h3)[i] = 0u;
        } else if (i < H3W + CW) {
            g_c[i - H3W] = 0.f;
        } else if (i < H3W + CW + BARW) {
            g_bar[i - H3W - CW] = 0u;
        } else {
            size_t j = i - H3W - CW - BARW;
            size_t per_t = (size_t)(NRP - NR) * (KPAD / 2);
            size_t t = j / per_t;
            size_t rem = j % per_t;
            size_t row = NR + rem / (KPAD / 2);
            size_t w = rem % (KPAD / 2);
            reinterpret_cast<unsigned*>(g_h2)[(t * NRP + row) * (KPAD / 2) + w] = 0u;
        }
    }
}

// ------------------------- launch 5: gates GEMM -> fragments ----------------
// grid (16 ct, 8 rt) = 128 blocks. W_ih 128-col stripe resident.
// Each block streams 384 independent (t, half) 32-row tiles, double-buffered.
__global__ __launch_bounds__(256) void k_gx() {
    extern __shared__ __align__(16) char smc[];
    unsigned smb = (unsigned)__cvta_generic_to_shared(smc);
    unsigned sWb = smb;
    unsigned sA0 = smb + GXW;
    unsigned mbW = smb + GXW + 2 * GXA;
    unsigned mb0 = mbW + 8;
    int tid = threadIdx.x, warp = tid >> 5, lane = tid & 31;
    int tg = lane & 3;
    int ct = blockIdx.x, rt = blockIdx.y;
    int bxl = rt * 16 + ct;

    if (tid == 0) { mbar_init(mbW, 1); mbar_init(mb0, 1); mbar_init(mb0 + 8, 1); }
    __syncthreads();
    if (tid == 0) {
        mbar_extx(mbW, GXW);
        const char* wsrc = (const char*)(g_WIHh + (size_t)ct * 128 * KPAD);
        bulkcp(sWb, wsrc, GXW / 2, mbW);
        bulkcp(sWb + GXW / 2, wsrc + GXW / 2, GXW / 2, mbW);
        // prefetch A tiles for i=0,1 (t=0, halves 0,1)
        mbar_extx(mb0, GXA);
        bulkcp(sA0, g_h2 + ((size_t)rt * 64) * KPAD, GXA, mb0);
        mbar_extx(mb0 + 8, GXA);
        bulkcp(sA0 + GXA, g_h2 + ((size_t)rt * 64 + 32) * KPAD, GXA, mb0 + 8);
    }

    int arow = (lane & 7) + ((lane >> 3) & 1) * 8;
    unsigned aR = (unsigned)(arow * (KPAD * 2)) + ((lane >> 4) & 1) * 16;
    int wn = warp * 16 + (lane & 7) + ((lane >> 4) & 1) * 8;
    unsigned wB = sWb + (unsigned)(wn * (KPAD * 2)) + ((lane >> 3) & 1) * 16;

    int c0 = ct * 128 + warp * 16 + 2 * tg;
    float2 bi0 = *(const float2*)&g_bias[c0];
    float2 bi1 = *(const float2*)&g_bias[c0 + 8];

    mbar_wait(mbW, 0);

    #pragma unroll 1
    for (int i = 0; i < 2 * TT; i++) {
        int t = i >> 1, half = i & 1;
        mbar_wait(mb0 + half * 8, t & 1);
        unsigned aB = sA0 + half * GXA;

        float d[2][2][4];
        #pragma unroll
        for (int mi = 0; mi < 2; mi++) {
            d[mi][0][0] = bi0.x; d[mi][0][1] = bi0.y; d[mi][0][2] = bi0.x; d[mi][0][3] = bi0.y;
            d[mi][1][0] = bi1.x; d[mi][1][1] = bi1.y; d[mi][1][2] = bi1.x; d[mi][1][3] = bi1.y;
        }
        #pragma unroll 4
        for (int c16 = 0; c16 < 32; c16++) {
            unsigned kB = (unsigned)(c16 * 32);
            unsigned b4[4], a0[4], a1[4];
            ldsm4(b4, wB + kB);
            ldsm4(a0, aB + aR + kB);
            ldsm4(a1, aB + aR + 16u * (KPAD * 2) + kB);
            mma16bf(d[0][0], a0, b4); mma16bf(d[0][1], a0, b4 + 2);
            mma16bf(d[1][0], a1, b4); mma16bf(d[1][1], a1, b4 + 2);
        }
        size_t base = ((size_t)(t * GRIDL + bxl) * 8) * 1024 + (size_t)tid * 4;
        #pragma unroll
        for (int mi = 0; mi < 2; mi++)
            #pragma unroll
            for (int ni = 0; ni < 2; ni++) {
                int f = (half * 2 + mi) * 2 + ni;
                *(float4*)&g_gt[base + (size_t)f * 1024] =
                    make_float4(d[mi][ni][0], d[mi][ni][1], d[mi][ni][2], d[mi][ni][3]);
            }
        __syncthreads();
        if (tid == 0 && i + 2 < 2 * TT) {
            int t2 = (i + 2) >> 1, h2 = (i + 2) & 1;
            unsigned mb = mb0 + h2 * 8;
            mbar_extx(mb, GXA);
            bulkcp(sA0 + h2 * GXA,
                   g_h2 + ((size_t)t2 * NRP + rt * 64 + h2 * 32) * KPAD, GXA, mb);
        }
    }
}

// ------------------------- launch 6: persistent LSTM ------------------------
// grid (16 ct, 8 rt) = 128 blocks. W_hh 128-col stripe resident; 64-row h stripe.
__global__ __launch_bounds__(256) void k_lstm() {
    extern __shared__ __align__(16) char smc[];
    unsigned smb = (unsigned)__cvta_generic_to_shared(smc);
    unsigned sWb = smb, sAb = smb + LSW, mbH = smb + LSW + LSA, mbW = mbH + 8;
    int tid = threadIdx.x, warp = tid >> 5, lane = tid & 31;
    int g = lane >> 2, tg = lane & 3;
    int ct = blockIdx.x, rt = blockIdx.y;
    int bxl = rt * 16 + ct;
    int R0 = rt * 64;
    int C0w = ct * 128 + warp * 16;

    if (tid == 0) { mbar_init(mbH, 1); mbar_init(mbW, 1); }
    __syncthreads();
    if (tid == 0) {
        mbar_extx(mbW, LSW);
        const char* wsrc = (const char*)(g_Whh + (size_t)ct * 128 * KPAD);
        bulkcp(sWb, wsrc, LSW / 2, mbW);
        bulkcp(sWb + LSW / 2, wsrc + LSW / 2, LSW / 2, mbW);
    }

    int arow = (lane & 7) + ((lane >> 3) & 1) * 8;
    unsigned akB = ((lane >> 4) & 1) * 16;
    unsigned aAdr[4];
    #pragma unroll
    for (int mi = 0; mi < 4; mi++)
        aAdr[mi] = sAb + (unsigned)((mi * 16 + arow) * (KPAD * 2)) + akB;
    int wn = warp * 16 + (lane & 7) + ((lane >> 4) & 1) * 8;
    unsigned wB = sWb + (unsigned)(wn * (KPAD * 2)) + ((lane >> 3) & 1) * 16;

    mbar_wait(mbW, 0);

    #pragma unroll 1
    for (int t = 0; t < TT; t++) {
        const unsigned short* hin = g_h3[(t + 2) % 3];
        unsigned short* hout = g_h3[t % 3];
        if (tid == 0) {
            mbar_extx(mbH, LSA);
            const char* src = (const char*)(hin + (size_t)R0 * KPAD);
            bulkcp(sAb, src, LSA / 2, mbH);
            bulkcp(sAb + LSA / 2, src + LSA / 2, LSA / 2, mbH);
        }
        // gates fragments (coalesced DRAM loads, overlap with bulk copy)
        float d[4][2][4];
        size_t gb = ((size_t)(t * GRIDL + bxl) * 8) * 1024 + (size_t)tid * 4;
        #pragma unroll
        for (int f = 0; f < 8; f++) {
            float4 v = *(const float4*)&g_gt[gb + (size_t)f * 1024];
            d[f >> 1][f & 1][0] = v.x; d[f >> 1][f & 1][1] = v.y;
            d[f >> 1][f & 1][2] = v.z; d[f >> 1][f & 1][3] = v.w;
        }
        mbar_wait(mbH, t & 1);

        #pragma unroll 4
        for (int c16 = 0; c16 < 32; c16++) {
            unsigned kB = (unsigned)(c16 * 32);
            unsigned b4[4], a[4][4];
            ldsm4(b4, wB + kB);
            #pragma unroll
            for (int mi = 0; mi < 4; mi++) ldsm4(a[mi], aAdr[mi] + kB);
            #pragma unroll
            for (int mi = 0; mi < 4; mi++) {
                mma16bf(d[mi][0], a[mi], b4);
                mma16bf(d[mi][1], a[mi], b4 + 2);
            }
        }

        // epilogue
        int last = (t == TT - 1);
        #pragma unroll
        for (int mi = 0; mi < 4; mi++) {
            #pragma unroll
            for (int ni = 0; ni < 2; ni++) {
                float d0 = d[mi][ni][0], d1 = d[mi][ni][1];
                float d2 = d[mi][ni][2], d3 = d[mi][ni][3];
                float e0 = __shfl_xor_sync(0xffffffffu, d0, 1);
                float e1 = __shfl_xor_sync(0xffffffffu, d1, 1);
                float e2 = __shfl_xor_sync(0xffffffffu, d2, 1);
                float e3 = __shfl_xor_sync(0xffffffffu, d3, 1);
                if ((lane & 1) == 0) {
                    int c0 = C0w + ni * 8 + 2 * tg;
                    int hc = c0 >> 2;
                    if (hc < HH) {
                        int rA = R0 + mi * 16 + g;
                        int rB = rA + 8;
                        float cA = g_c[hc * NRP + rA];
                        float ig = fsig(d0), fg = fsig(d1), gg = ftanh(e0), og = fsig(e1);
                        float cn = fmaf(fg, cA, ig * gg);
                        g_c[hc * NRP + rA] = cn;
                        float hv = og * ftanh(cn);
                        hout[(size_t)rA * KPAD + hc] = f2bf(hv);
                        if (last) g_hF[hc * NRP + rA] = hv;
                        float cB = g_c[hc * NRP + rB];
                        ig = fsig(d2); fg = fsig(d3); gg = ftanh(e2); og = fsig(e3);
                        cn = fmaf(fg, cB, ig * gg);
                        g_c[hc * NRP + rB] = cn;
                        hv = og * ftanh(cn);
                        hout[(size_t)rB * KPAD + hc] = f2bf(hv);
                        if (last) g_hF[hc * NRP + rB] = hv;
                    }
                }
            }
        }

        // grid barrier
        __threadfence();
        __syncthreads();
        if (tid == 0) {
            atomicAdd(&g_bar[t], 1u);
            while (*(volatile unsigned*)&g_bar[t] < (unsigned)GRIDL) {}
        }
        __syncthreads();
        __threadfence();
    }
}

// ------------------------- h_last transpose -------------------------
__global__ void k_trh() {
    int idx = blockIdx.x * 256 + threadIdx.x;
    if (idx >= NR * HH) return;
    int n = idx / HH, k = idx % HH;
    g_hT[idx] = g_hF[k * NRP + n];
}

// ------------------------- tf32 MMA GEMM: C = act(A @ W + b) ----------------
__device__ __forceinline__ float* selbuf(int s) {
    switch (s) {
        case 0: return g_hT;
        case 1: return g_z1;
        case 2: return g_z2;
        default: return g_z3;
    }
}

__global__ __launch_bounds__(256) void k_gemmt(int aSel, const float* __restrict__ W,
                                               const float* __restrict__ bias, int cSel,
                                               int M, int K, int N, int doRelu) {
    const float* A = selbuf(aSel);
    float* C = selbuf(cSel);
    __shared__ __align__(16) float As[64 * 36];
    __shared__ __align__(16) float Ws[32 * 72];
    int tid  = threadIdx.x;
    int warp = tid >> 5;
    int lane = tid & 31;
    int g  = lane >> 2;
    int tg = lane & 3;
    int n0 = blockIdx.x * 64, m0 = blockIdx.y * 64;
    int wm = (warp >> 2) * 32;
    int wn = (warp & 3) * 16;

    int ami = tid >> 2;
    int akq = (tid & 3) * 8;
    int wkk = tid >> 3;
    int wnq = (tid & 7) * 8;

    float d[2][2][4];
    #pragma unroll
    for (int i = 0; i < 2; i++)
        #pragma unroll
        for (int j = 0; j < 2; j++)
            #pragma unroll
            for (int q = 0; q < 4; q++) d[i][j][q] = 0.f;

    int nslab = (K + 31) / 32;
    float rA[8], rW[8];

    {
        int m = m0 + ami;
        #pragma unroll
        for (int j = 0; j < 8; j++) {
            int k = akq + j;
            rA[j] = (m < M && k < K) ? A[(size_t)m * K + k] : 0.f;
        }
        #pragma unroll
        for (int j = 0; j < 8; j++) {
            int n = n0 + wnq + j;
            rW[j] = (wkk < K && n < N) ? W[(size_t)wkk * N + n] : 0.f;
        }
    }

    #pragma unroll 1
    for (int s = 0; s < nslab; s++) {
        #pragma unroll
        for (int j = 0; j < 8; j++) As[ami * 36 + akq + j] = tf32r(rA[j]);
        #pragma unroll
        for (int j = 0; j < 8; j++) Ws[wkk * 72 + wnq + j] = tf32r(rW[j]);
        __syncthreads();
        if (s + 1 < nslab) {
            int k0 = (s + 1) * 32;
            int m = m0 + ami;
            #pragma unroll
            for (int j = 0; j < 8; j++) {
                int k = k0 + akq + j;
                rA[j] = (m < M && k < K) ? A[(size_t)m * K + k] : 0.f;
            }
            #pragma unroll
            for (int j = 0; j < 8; j++) {
                int k = k0 + wkk;
                int n = n0 + wnq + j;
                rW[j] = (k < K && n < N) ? W[(size_t)k * N + n] : 0.f;
            }
        }
        const unsigned* Asu = reinterpret_cast<const unsigned*>(As);
        const unsigned* Wsu = reinterpret_cast<const unsigned*>(Ws);
        #pragma unroll
        for (int c8 = 0; c8 < 4; c8++) {
            int kc = c8 * 8;
            unsigned a[2][4], b[2][2];
            #pragma unroll
            for (int mi = 0; mi < 2; mi++) {
                int mbase = (wm + mi * 16 + g) * 36 + kc;
                a[mi][0] = Asu[mbase + tg];
                a[mi][1] = Asu[mbase + 8 * 36 + tg];
                a[mi][2] = Asu[mbase + tg + 4];
                a[mi][3] = Asu[mbase + 8 * 36 + tg + 4];
            }
            #pragma unroll
            for (int ni = 0; ni < 2; ni++) {
                int nb = wn + ni * 8 + g;
                b[ni][0] = Wsu[(kc + tg) * 72 + nb];
                b[ni][1] = Wsu[(kc + tg + 4) * 72 + nb];
            }
            #pragma unroll
            for (int mi = 0; mi < 2; mi++)
                #pragma unroll
                for (int ni = 0; ni < 2; ni++)
                    mma8(d[mi][ni], a[mi], b[ni]);
        }
        __syncthreads();
    }

    #pragma unroll
    for (int mi = 0; mi < 2; mi++) {
        #pragma unroll
        for (int ni = 0; ni < 2; ni++) {
            int mA = m0 + wm + mi * 16 + g;
            int mB = mA + 8;
            int n  = n0 + wn + ni * 8 + 2 * tg;
            float b0 = (n < N)     ? bias[n]     : 0.f;
            float b1 = (n + 1 < N) ? bias[n + 1] : 0.f;
            float v;
            if (mA < M) {
                if (n < N) {
                    v = d[mi][ni][0] + b0;
                    C[(size_t)mA * N + n] = doRelu ? fmaxf(v, 0.f) : v;
                }
                if (n + 1 < N) {
                    v = d[mi][ni][1] + b1;
                    C[(size_t)mA * N + n + 1] = doRelu ? fmaxf(v, 0.f) : v;
                }
            }
            if (mB < M) {
                if (n < N) {
                    v = d[mi][ni][2] + b0;
                    C[(size_t)mB * N + n] = doRelu ? fmaxf(v, 0.f) : v;
                }
                if (n + 1 < N) {
                    v = d[mi][ni][3] + b1;
                    C[(size_t)mB * N + n + 1] = doRelu ? fmaxf(v, 0.f) : v;
                }
            }
        }
    }
}

// ------------------------- final layer -------------------------
__global__ void k_final(const float* __restrict__ Wh4, const float* __restrict__ bh4,
                        float* __restrict__ out) {
    __shared__ float zs[M1];
    int n = blockIdx.x;
    int tid = threadIdx.x;
    for (int k = tid; k < M1; k += 256) zs[k] = g_z3[n * M1 + k];
    __syncthreads();
    int w = tid >> 5, lane = tid & 31;
    #pragma unroll
    for (int oi = 0; oi < 3; oi++) {
        int o = w + oi * 8;
        float p = 0.f;
        for (int k = lane; k < M1; k += 32) p = fmaf(zs[k], Wh4[k * OD + o], p);
        #pragma unroll
        for (int off = 16; off; off >>= 1) p += __shfl_down_sync(0xffffffffu, p, off);
        if (lane == 0) {
            float y = fsig(p + bh4[o]);
            int b = n / LL, l = n % LL;
            out[(b * OD + o) * LL + l] = y;
        }
    }
}

// ------------------------- launcher -------------------------
extern "C" void kernel_launch(void* const* d_in, const int* in_sizes, int n_in,
                              void* d_out, int out_size) {
    const float* x    = (const float*)d_in[0];
    const float* Ahat = (const float*)d_in[1];
    const float* W1   = (const float*)d_in[2];
    const float* W2   = (const float*)d_in[3];
    const float* W_ih = (const float*)d_in[4];
    const float* W_hh = (const float*)d_in[5];
    const float* b_ih = (const float*)d_in[6];
    const float* b_hh = (const float*)d_in[7];
    const float* Wh1  = (const float*)d_in[8];
    const float* bh1  = (const float*)d_in[9];
    const float* Wh2  = (const float*)d_in[10];
    const float* bh2  = (const float*)d_in[11];
    const float* Wh3  = (const float*)d_in[12];
    const float* bh3  = (const float*)d_in[13];
    const float* Wh4  = (const float*)d_in[14];
    const float* bh4  = (const float*)d_in[15];
    float* out = (float*)d_out;

    cudaFuncSetAttribute(k_gx,   cudaFuncAttributeMaxDynamicSharedMemorySize, SMEMG);
    cudaFuncSetAttribute(k_lstm, cudaFuncAttributeMaxDynamicSharedMemorySize, SMEML);

    // launches 1-5 so that k_lstm is launch #6 (ncu -s 5 -c 1 target)
    k_pn<<<1, 512>>>(W1, W2);
    k_wcvt<<<dim3(H4, 2), 256>>>(W_ih, W_hh, b_ih, b_hh);
    k_front<<<BB * TT, 256>>>(x, Ahat);
    k_zero<<<1024, 256>>>();
    k_gx<<<dim3(16, 8), 256, SMEMG>>>();
    k_lstm<<<dim3(16, 8), 256, SMEML>>>();

    k_trh<<<(NR * HH + 255) / 256, 256>>>();
    k_gemmt<<<dim3(47, 8), 256>>>(0, Wh1, bh1, 1, NR, HH, M1, 1);
    k_gemmt<<<dim3(16, 8), 256>>>(1, Wh2, bh2, 2, NR, M1, M2, 1);
    k_gemmt<<<dim3(47, 8), 256>>>(2, Wh3, bh3, 3, NR, M2, M1, 1);
    k_final<<<NR, 256>>>(Wh4, bh4, out);
}

// round 11
// speedup vs baseline: 1.3090x; 1.3090x over previous
#include <cuda_runtime.h>
#include <cuda_bf16.h>
#include <math.h>

#define BB 4
#define TT 192
#define LL 120
#define GG 500
#define HH 500      // HL
#define H4 2000
#define H4P 2048
#define KPAD 520    // padded K (bf16 units); 1040B row stride -> LDSM conflict-free
#define NR 480
#define NRP 512
#define OD 24
#define M1 3000
#define M2 1000

// k_lstm tiling: 128 blocks = 16 col-tiles(128 gate-cols) x 8 row-tiles(64 rows)
#define GRIDL 128
#define LSW (128 * KPAD * 2)    // 133120 W stripe bytes (resident)
#define LSA (64 * KPAD * 2)     // 66560 h stripe bytes
#define SMEML (LSW + LSA + 32)

// ------------------------- scratch (device globals) -------------------------
__device__ float g_P[GG];
__device__ float g_Nv[GG];
__device__ float g_rho[GG];
__device__ float g_esign[GG];
__device__ int   g_ef[GG];
__device__ int   g_act0[GG];
__device__ int   g_nev[1];
__device__ __align__(16) float g_bias[H4P];                   // interleaved cq = hc*4+gate
__device__ __align__(16) float g_WihTp[GG * H4P];             // fp32 [f][cq]
__device__ __align__(16) float g_TAB[(GG + 1) * H4P * 2];     // [s][cq*2 + {A,B}]
__device__ __align__(16) unsigned short g_Whh[H4P * KPAD];    // bf16 W_hh [cq][k]
__device__ __align__(16) float4 g_uvs[TT * NRP];              // (u, v, seg-bits, 0)
__device__ __align__(16) unsigned short g_h3[3][NRP * KPAD];  // bf16 h ring [row][k]
__device__ __align__(16) float g_c[HH * NRP];                 // c fp32 [hc][row]
__device__ __align__(16) float g_hF[HH * NRP];                // fp32 h_last [hc][row]
__device__ unsigned g_bar[TT];
__device__ __align__(16) float g_hT[NR * HH];
__device__ __align__(16) float g_z1[NR * M1];
__device__ __align__(16) float g_z2[NR * M2];
__device__ __align__(16) float g_z3[NR * M1];

// ------------------------- helpers -------------------------
__device__ __forceinline__ float fsig(float x) {
    return __fdividef(1.f, 1.f + __expf(-x));
}
__device__ __forceinline__ float ftanh(float x) {
    float ax = fabsf(x);
    float t  = __expf(-2.f * ax);
    float r  = __fdividef(1.f - t, 1.f + t);
    return copysignf(r, x);
}
__device__ __forceinline__ float tf32r(float x) {
    unsigned r;
    asm("cvt.rna.tf32.f32 %0, %1;" : "=r"(r) : "f"(x));
    return __uint_as_float(r);
}
__device__ __forceinline__ unsigned short f2bf(float v) {
    __nv_bfloat16 b = __float2bfloat16_rn(v);
    return *reinterpret_cast<unsigned short*>(&b);
}
__device__ __forceinline__ void mbar_init(unsigned a, unsigned c) {
    asm volatile("mbarrier.init.shared.b64 [%0], %1;" :: "r"(a), "r"(c) : "memory");
}
__device__ __forceinline__ void mbar_extx(unsigned a, unsigned tx) {
    asm volatile("mbarrier.arrive.expect_tx.shared.b64 _, [%0], %1;" :: "r"(a), "r"(tx) : "memory");
}
__device__ __forceinline__ void mbar_wait(unsigned a, unsigned ph) {
    asm volatile(
        "{\n\t.reg .pred P;\n"
        "W%=:\n\t"
        "mbarrier.try_wait.parity.acquire.cta.shared::cta.b64 P, [%0], %1, 0x989680;\n\t"
        "@P bra D%=;\n\t"
        "bra W%=;\n"
        "D%=:\n\t}"
        :: "r"(a), "r"(ph) : "memory");
}
__device__ __forceinline__ void bulkcp(unsigned dst, const void* src, unsigned bytes, unsigned mbar) {
    asm volatile(
        "cp.async.bulk.shared::cta.global.mbarrier::complete_tx::bytes [%0], [%1], %2, [%3];"
        :: "r"(dst), "l"(src), "r"(bytes), "r"(mbar) : "memory");
}
__device__ __forceinline__ void ldsm4(unsigned* r, unsigned addr) {
    asm volatile("ldmatrix.sync.aligned.m8n8.x4.shared.b16 {%0,%1,%2,%3}, [%4];"
                 : "=r"(r[0]), "=r"(r[1]), "=r"(r[2]), "=r"(r[3]) : "r"(addr));
}
__device__ __forceinline__ void mma16bf(float* d, const unsigned* a, const unsigned* b) {
    asm volatile(
        "mma.sync.aligned.m16n8k16.row.col.f32.bf16.bf16.f32 "
        "{%0,%1,%2,%3}, {%4,%5,%6,%7}, {%8,%9}, {%0,%1,%2,%3};"
        : "+f"(d[0]), "+f"(d[1]), "+f"(d[2]), "+f"(d[3])
        : "r"(a[0]), "r"(a[1]), "r"(a[2]), "r"(a[3]), "r"(b[0]), "r"(b[1]));
}
__device__ __forceinline__ void mma8(float* d, const unsigned* a, const unsigned* b) {
    asm volatile(
        "mma.sync.aligned.m16n8k8.row.col.f32.tf32.tf32.f32 "
        "{%0,%1,%2,%3}, {%4,%5,%6,%7}, {%8,%9}, {%0,%1,%2,%3};"
        : "+f"(d[0]), "+f"(d[1]), "+f"(d[2]), "+f"(d[3])
        : "r"(a[0]), "r"(a[1]), "r"(a[2]), "r"(a[3]), "r"(b[0]), "r"(b[1]));
}

// ------------------------- launch 1: P,N + breakpoint events (1 block) ------
__global__ void k_setup1(const float* __restrict__ W1, const float* __restrict__ W2) {
    __shared__ float srho[GG];
    __shared__ float ssg[GG];
    __shared__ int   sf[GG];
    __shared__ int   cnt;
    int tid = threadIdx.x;
    if (tid < GG) {
        float p = 0.f, n = 0.f;
        for (int g = 0; g < GG; g++) {
            float w = W1[g];
            float v = W2[g * GG + tid];
            p = fmaf(fmaxf(w, 0.f), v, p);
            n = fmaf(fmaxf(-w, 0.f), v, n);
        }
        g_P[tid]  = p;
        g_Nv[tid] = n;
    }
    if (tid == 0) cnt = 0;
    __syncthreads();
    if (tid < GG) {
        float p = g_P[tid], n = g_Nv[tid];
        int act0 = 0;
        float sgn = 0.f, rho = 0.f;
        if (n > 0.f) {
            if (p >= 0.f) { act0 = 1; }
            else { act0 = 0; rho = __fdividef(-p, n); sgn = 1.f; }
        } else if (n < 0.f) {
            if (p > 0.f) { act0 = 1; rho = __fdividef(p, -n); sgn = -1.f; }
            else { act0 = 0; }
        } else {
            act0 = (p > 0.f) ? 1 : 0;
        }
        g_act0[tid] = act0;
        if (sgn != 0.f) {
            int e = atomicAdd(&cnt, 1);
            srho[e] = rho; ssg[e] = sgn; sf[e] = tid;
        }
    }
    __syncthreads();
    int E = cnt;
    if (tid == 0) g_nev[0] = E;
    if (tid < E) {
        float r = srho[tid];
        int rank = 0;
        for (int j = 0; j < E; j++) {
            float rj = srho[j];
            rank += (rj < r) || (rj == r && j < tid);
        }
        g_rho[rank]   = r;
        g_esign[rank] = ssg[tid];
        g_ef[rank]    = sf[tid];
    }
}

// ------------------------- launch 2: weight reshuffles + bias ---------------
// grid (16,126): y<63 -> WihTp transpose tiles; y>=63 -> Whh bf16 rows + bias.
__global__ void k_trans(const float* __restrict__ W_ih, const float* __restrict__ W_hh,
                        const float* __restrict__ b_ih, const float* __restrict__ b_hh) {
    __shared__ float tle[32][33];
    int x = threadIdx.x, y = threadIdx.y;
    if (blockIdx.y < 63) {
        // g_WihTp[f][cq(h)] = W_ih[h][f]
        int f0 = blockIdx.x * 32;
        int h0 = blockIdx.y * 32;
        for (int i = y; i < 32; i += 8) {
            int h = h0 + i, f = f0 + x;
            tle[i][x] = (h < H4 && f < GG) ? W_ih[(size_t)h * GG + f] : 0.f;
        }
        __syncthreads();
        for (int i = y; i < 32; i += 8) {
            int f = f0 + i, h = h0 + x;
            if (f < GG && h < H4) {
                int cq = (h % HH) * 4 + h / HH;
                g_WihTp[(size_t)f * H4P + cq] = tle[x][i];
            }
        }
    } else {
        // g_Whh[cq(h)][k] = bf16(W_hh[h][k]); k pad [500,512) zeroed here
        int r0 = (blockIdx.y - 63) * 32;
        int k0 = blockIdx.x * 32;
        for (int i = y; i < 32; i += 8) {
            int h = r0 + i;
            if (h < H4) {
                int cq = (h % HH) * 4 + h / HH;
                int k = k0 + x;
                g_Whh[(size_t)cq * KPAD + k] = (k < GG) ? f2bf(W_hh[(size_t)h * HH + k])
                                                        : (unsigned short)0;
            }
        }
        if (blockIdx.x == 0 && blockIdx.y == 125) {
            int tid = y * 32 + x;
            for (int h = tid; h < H4; h += 256) {
                int cq = (h % HH) * 4 + h / HH;
                g_bias[cq] = b_ih[h] + b_hh[h];
            }
        }
    }
}

// ------------------------- launch 3: interleaved segment tables -------------
// 8 blocks x 256: thread = one interleaved col cq; coalesced WihTp scans.
__global__ void k_tables() {
    int cq = blockIdx.x * 256 + threadIdx.x;   // 0..2047
    float accA = 0.f, accB = 0.f;
    for (int f = 0; f < GG; f++) {
        if (g_act0[f]) {
            float w = g_WihTp[(size_t)f * H4P + cq];
            accA = fmaf(w, g_P[f],  accA);
            accB = fmaf(w, g_Nv[f], accB);
        }
    }
    g_TAB[(size_t)cq * 2]     = accA;
    g_TAB[(size_t)cq * 2 + 1] = accB;
    int E = g_nev[0];
    for (int e = 0; e < E; e++) {
        int f = g_ef[e];
        float w = g_WihTp[(size_t)f * H4P + cq] * g_esign[e];
        accA = fmaf(w, g_P[f],  accA);
        accB = fmaf(w, g_Nv[f], accB);
        size_t base = (size_t)(e + 1) * (H4P * 2) + (size_t)cq * 2;
        g_TAB[base]     = accA;
        g_TAB[base + 1] = accB;
    }
}

// ------------------------- launch 4: GCN front -> u,v,seg -------------------
__global__ void k_front(const float* __restrict__ x, const float* __restrict__ Ahat) {
    __shared__ float xr[LL], sp[LL], sn[LL];
    int bid = blockIdx.x;
    int b = bid / TT, t = bid % TT;
    int tid = threadIdx.x;
    if (tid < LL) xr[tid] = x[(b * TT + t) * LL + tid];
    __syncthreads();
    if (tid < LL) {
        float s = 0.f;
        const float* Ar = &Ahat[tid * LL];
        for (int l = 0; l < LL; l++) s = fmaf(Ar[l], xr[l], s);
        sp[tid] = fmaxf(s, 0.f);
        sn[tid] = fmaxf(-s, 0.f);
    }
    __syncthreads();
    if (tid < LL) {
        float uu = 0.f, vv = 0.f;
        const float* Ar = &Ahat[tid * LL];
        for (int l = 0; l < LL; l++) {
            uu = fmaf(Ar[l], sp[l], uu);
            vv = fmaf(Ar[l], sn[l], vv);
        }
        int E = g_nev[0];
        int s;
        if (uu > 0.f) {
            float rho = vv / uu;
            int lo = 0, hi = E;
            while (lo < hi) {
                int mid = (lo + hi) >> 1;
                if (g_rho[mid] < rho) lo = mid + 1; else hi = mid;
            }
            s = lo;
        } else {
            s = (vv > 0.f) ? E : 0;
        }
        g_uvs[t * NRP + b * LL + tid] = make_float4(uu, vv, __int_as_float(s), 0.f);
    }
}

// ------------------------- launch 5: per-replay zero init -------------------
__global__ void k_zero() {
    const size_t H3W  = 3ull * NRP * KPAD / 2;              // u32 words of h ring
    const size_t CW   = (size_t)HH * NRP;                   // floats of c
    const size_t BARW = TT;
    const size_t UVSW = (size_t)TT * (NRP - NR);            // pad float4 slots
    const size_t TOTAL = H3W + CW + BARW + UVSW;
    size_t stride = (size_t)gridDim.x * 256;
    for (size_t i = (size_t)blockIdx.x * 256 + threadIdx.x; i < TOTAL; i += stride) {
        if (i < H3W) {
            reinterpret_cast<unsigned*>(g_h3)[i] = 0u;
        } else if (i < H3W + CW) {
            g_c[i - H3W] = 0.f;
        } else if (i < H3W + CW + BARW) {
            g_bar[i - H3W - CW] = 0u;
        } else {
            size_t j = i - H3W - CW - BARW;
            size_t t = j / (NRP - NR);
            size_t r = NR + j % (NRP - NR);
            g_uvs[t * NRP + r] = make_float4(0.f, 0.f, 0.f, 0.f);
        }
    }
}

// ------------------------- launch 6: persistent LSTM ------------------------
// 128 blocks = 16 ct (128 gate-cols) x 8 rt (64 rows). W_hh stripe resident.
__global__ __launch_bounds__(256) void k_lstm() {
    extern __shared__ __align__(16) char smc[];
    unsigned smb = (unsigned)__cvta_generic_to_shared(smc);
    unsigned sWb = smb, sAb = smb + LSW, mbH = smb + LSW + LSA, mbW = mbH + 8;
    int tid = threadIdx.x, warp = tid >> 5, lane = tid & 31;
    int g = lane >> 2, tg = lane & 3;
    int ct = blockIdx.x, rt = blockIdx.y;
    int R0 = rt * 64;
    int C0w = ct * 128 + warp * 16;

    if (tid == 0) { mbar_init(mbH, 1); mbar_init(mbW, 1); }
    __syncthreads();
    if (tid == 0) {
        mbar_extx(mbW, LSW);
        const char* wsrc = (const char*)(g_Whh + (size_t)ct * 128 * KPAD);
        bulkcp(sWb, wsrc, LSW / 2, mbW);
        bulkcp(sWb + LSW / 2, wsrc + LSW / 2, LSW / 2, mbW);
    }

    int arow = (lane & 7) + ((lane >> 3) & 1) * 8;
    unsigned akB = ((lane >> 4) & 1) * 16;
    unsigned aAdr[4];
    #pragma unroll
    for (int mi = 0; mi < 4; mi++)
        aAdr[mi] = sAb + (unsigned)((mi * 16 + arow) * (KPAD * 2)) + akB;
    int wn = warp * 16 + (lane & 7) + ((lane >> 4) & 1) * 8;
    unsigned wB = sWb + (unsigned)(wn * (KPAD * 2)) + ((lane >> 3) & 1) * 16;

    int cA0 = C0w + 2 * tg;
    float2 bi0 = *(const float2*)&g_bias[cA0];
    float2 bi1 = *(const float2*)&g_bias[cA0 + 8];

    mbar_wait(mbW, 0);

    #pragma unroll 1
    for (int t = 0; t < TT; t++) {
        const unsigned short* hin = g_h3[(t + 2) % 3];
        unsigned short* hout = g_h3[t % 3];
        if (tid == 0) {
            mbar_extx(mbH, LSA);
            const char* src = (const char*)(hin + (size_t)R0 * KPAD);
            bulkcp(sAb, src, LSA / 2, mbH);
            bulkcp(sAb + LSA / 2, src + LSA / 2, LSA / 2, mbH);
        }

        // prologue: gates_x via interleaved PWL table (overlaps bulk copy)
        float d[4][2][4];
        #pragma unroll
        for (int mi = 0; mi < 4; mi++) {
            int rA = R0 + mi * 16 + g;
            float4 pa = g_uvs[t * NRP + rA];
            float4 pb = g_uvs[t * NRP + rA + 8];
            const float4* TA = (const float4*)&g_TAB[(size_t)__float_as_int(pa.z) * (H4P * 2)];
            const float4* TB = (const float4*)&g_TAB[(size_t)__float_as_int(pb.z) * (H4P * 2)];
            #pragma unroll
            for (int ni = 0; ni < 2; ni++) {
                int c = cA0 + ni * 8;            // even
                float4 qa = TA[c >> 1];          // A(c),B(c),A(c+1),B(c+1)
                float4 qb = TB[c >> 1];
                float2 bi = ni ? bi1 : bi0;
                d[mi][ni][0] = fmaf(pa.x, qa.x, fmaf(pa.y, qa.y, bi.x));
                d[mi][ni][1] = fmaf(pa.x, qa.z, fmaf(pa.y, qa.w, bi.y));
                d[mi][ni][2] = fmaf(pb.x, qb.x, fmaf(pb.y, qb.y, bi.x));
                d[mi][ni][3] = fmaf(pb.x, qb.z, fmaf(pb.y, qb.w, bi.y));
            }
        }

        mbar_wait(mbH, t & 1);

        #pragma unroll 4
        for (int c16 = 0; c16 < 32; c16++) {
            unsigned kB = (unsigned)(c16 * 32);
            unsigned b4[4], a[4][4];
            ldsm4(b4, wB + kB);
            #pragma unroll
            for (int mi = 0; mi < 4; mi++) ldsm4(a[mi], aAdr[mi] + kB);
            #pragma unroll
            for (int mi = 0; mi < 4; mi++) {
                mma16bf(d[mi][0], a[mi], b4);
                mma16bf(d[mi][1], a[mi], b4 + 2);
            }
        }

        // epilogue
        int last = (t == TT - 1);
        #pragma unroll
        for (int mi = 0; mi < 4; mi++) {
            #pragma unroll
            for (int ni = 0; ni < 2; ni++) {
                float d0 = d[mi][ni][0], d1 = d[mi][ni][1];
                float d2 = d[mi][ni][2], d3 = d[mi][ni][3];
                float e0 = __shfl_xor_sync(0xffffffffu, d0, 1);
                float e1 = __shfl_xor_sync(0xffffffffu, d1, 1);
                float e2 = __shfl_xor_sync(0xffffffffu, d2, 1);
                float e3 = __shfl_xor_sync(0xffffffffu, d3, 1);
                if ((lane & 1) == 0) {
                    int c0 = C0w + ni * 8 + 2 * tg;
                    int hc = c0 >> 2;
                    if (hc < HH) {
                        int rA = R0 + mi * 16 + g;
                        int rB = rA + 8;
                        float cA = g_c[hc * NRP + rA];
                        float ig = fsig(d0), fg = fsig(d1), gg = ftanh(e0), og = fsig(e1);
                        float cn = fmaf(fg, cA, ig * gg);
                        g_c[hc * NRP + rA] = cn;
                        float hv = og * ftanh(cn);
                        hout[(size_t)rA * KPAD + hc] = f2bf(hv);
                        if (last) g_hF[hc * NRP + rA] = hv;
                        float cB = g_c[hc * NRP + rB];
                        ig = fsig(d2); fg = fsig(d3); gg = ftanh(e2); og = fsig(e3);
                        cn = fmaf(fg, cB, ig * gg);
                        g_c[hc * NRP + rB] = cn;
                        hv = og * ftanh(cn);
                        hout[(size_t)rB * KPAD + hc] = f2bf(hv);
                        if (last) g_hF[hc * NRP + rB] = hv;
                    }
                }
            }
        }

        // grid barrier
        __threadfence();
        __syncthreads();
        if (tid == 0) {
            atomicAdd(&g_bar[t], 1u);
            while (*(volatile unsigned*)&g_bar[t] < (unsigned)GRIDL) {}
        }
        __syncthreads();
        __threadfence();
    }
}

// ------------------------- h_last transpose -------------------------
__global__ void k_trh() {
    int idx = blockIdx.x * 256 + threadIdx.x;
    if (idx >= NR * HH) return;
    int n = idx / HH, k = idx % HH;
    g_hT[idx] = g_hF[k * NRP + n];
}

// ------------------------- tf32 MMA GEMM: C = act(A @ W + b) ----------------
__device__ __forceinline__ float* selbuf(int s) {
    switch (s) {
        case 0: return g_hT;
        case 1: return g_z1;
        case 2: return g_z2;
        default: return g_z3;
    }
}

__global__ __launch_bounds__(256) void k_gemmt(int aSel, const float* __restrict__ W,
                                               const float* __restrict__ bias, int cSel,
                                               int M, int K, int N, int doRelu) {
    const float* A = selbuf(aSel);
    float* C = selbuf(cSel);
    __shared__ __align__(16) float As[64 * 36];
    __shared__ __align__(16) float Ws[32 * 72];
    int tid  = threadIdx.x;
    int warp = tid >> 5;
    int lane = tid & 31;
    int g  = lane >> 2;
    int tg = lane & 3;
    int n0 = blockIdx.x * 64, m0 = blockIdx.y * 64;
    int wm = (warp >> 2) * 32;
    int wn = (warp & 3) * 16;

    int ami = tid >> 2;
    int akq = (tid & 3) * 8;
    int wkk = tid >> 3;
    int wnq = (tid & 7) * 8;

    float d[2][2][4];
    #pragma unroll
    for (int i = 0; i < 2; i++)
        #pragma unroll
        for (int j = 0; j < 2; j++)
            #pragma unroll
            for (int q = 0; q < 4; q++) d[i][j][q] = 0.f;

    int nslab = (K + 31) / 32;
    float rA[8], rW[8];

    {
        int m = m0 + ami;
        #pragma unroll
        for (int j = 0; j < 8; j++) {
            int k = akq + j;
            rA[j] = (m < M && k < K) ? A[(size_t)m * K + k] : 0.f;
        }
        #pragma unroll
        for (int j = 0; j < 8; j++) {
            int n = n0 + wnq + j;
            rW[j] = (wkk < K && n < N) ? W[(size_t)wkk * N + n] : 0.f;
        }
    }

    #pragma unroll 1
    for (int s = 0; s < nslab; s++) {
        #pragma unroll
        for (int j = 0; j < 8; j++) As[ami * 36 + akq + j] = tf32r(rA[j]);
        #pragma unroll
        for (int j = 0; j < 8; j++) Ws[wkk * 72 + wnq + j] = tf32r(rW[j]);
        __syncthreads();
        if (s + 1 < nslab) {
            int k0 = (s + 1) * 32;
            int m = m0 + ami;
            #pragma unroll
            for (int j = 0; j < 8; j++) {
                int k = k0 + akq + j;
                rA[j] = (m < M && k < K) ? A[(size_t)m * K + k] : 0.f;
            }
            #pragma unroll
            for (int j = 0; j < 8; j++) {
                int k = k0 + wkk;
                int n = n0 + wnq + j;
                rW[j] = (k < K && n < N) ? W[(size_t)k * N + n] : 0.f;
            }
        }
        const unsigned* Asu = reinterpret_cast<const unsigned*>(As);
        const unsigned* Wsu = reinterpret_cast<const unsigned*>(Ws);
        #pragma unroll
        for (int c8 = 0; c8 < 4; c8++) {
            int kc = c8 * 8;
            unsigned a[2][4], b[2][2];
            #pragma unroll
            for (int mi = 0; mi < 2; mi++) {
                int mbase = (wm + mi * 16 + g) * 36 + kc;
                a[mi][0] = Asu[mbase + tg];
                a[mi][1] = Asu[mbase + 8 * 36 + tg];
                a[mi][2] = Asu[mbase + tg + 4];
                a[mi][3] = Asu[mbase + 8 * 36 + tg + 4];
            }
            #pragma unroll
            for (int ni = 0; ni < 2; ni++) {
                int nb = wn + ni * 8 + g;
                b[ni][0] = Wsu[(kc + tg) * 72 + nb];
                b[ni][1] = Wsu[(kc + tg + 4) * 72 + nb];
            }
            #pragma unroll
            for (int mi = 0; mi < 2; mi++)
                #pragma unroll
                for (int ni = 0; ni < 2; ni++)
                    mma8(d[mi][ni], a[mi], b[ni]);
        }
        __syncthreads();
    }

    #pragma unroll
    for (int mi = 0; mi < 2; mi++) {
        #pragma unroll
        for (int ni = 0; ni < 2; ni++) {
            int mA = m0 + wm + mi * 16 + g;
            int mB = mA + 8;
            int n  = n0 + wn + ni * 8 + 2 * tg;
            float b0 = (n < N)     ? bias[n]     : 0.f;
            float b1 = (n + 1 < N) ? bias[n + 1] : 0.f;
            float v;
            if (mA < M) {
                if (n < N) {
                    v = d[mi][ni][0] + b0;
                    C[(size_t)mA * N + n] = doRelu ? fmaxf(v, 0.f) : v;
                }
                if (n + 1 < N) {
                    v = d[mi][ni][1] + b1;
                    C[(size_t)mA * N + n + 1] = doRelu ? fmaxf(v, 0.f) : v;
                }
            }
            if (mB < M) {
                if (n < N) {
                    v = d[mi][ni][2] + b0;
                    C[(size_t)mB * N + n] = doRelu ? fmaxf(v, 0.f) : v;
                }
                if (n + 1 < N) {
                    v = d[mi][ni][3] + b1;
                    C[(size_t)mB * N + n + 1] = doRelu ? fmaxf(v, 0.f) : v;
                }
            }
        }
    }
}

// ------------------------- final layer -------------------------
__global__ void k_final(const float* __restrict__ Wh4, const float* __restrict__ bh4,
                        float* __restrict__ out) {
    __shared__ float zs[M1];
    int n = blockIdx.x;
    int tid = threadIdx.x;
    for (int k = tid; k < M1; k += 256) zs[k] = g_z3[n * M1 + k];
    __syncthreads();
    int w = tid >> 5, lane = tid & 31;
    #pragma unroll
    for (int oi = 0; oi < 3; oi++) {
        int o = w + oi * 8;
        float p = 0.f;
        for (int k = lane; k < M1; k += 32) p = fmaf(zs[k], Wh4[k * OD + o], p);
        #pragma unroll
        for (int off = 16; off; off >>= 1) p += __shfl_down_sync(0xffffffffu, p, off);
        if (lane == 0) {
            float y = fsig(p + bh4[o]);
            int b = n / LL, l = n % LL;
            out[(b * OD + o) * LL + l] = y;
        }
    }
}

// ------------------------- launcher -------------------------
extern "C" void kernel_launch(void* const* d_in, const int* in_sizes, int n_in,
                              void* d_out, int out_size) {
    const float* x    = (const float*)d_in[0];
    const float* Ahat = (const float*)d_in[1];
    const float* W1   = (const float*)d_in[2];
    const float* W2   = (const float*)d_in[3];
    const float* W_ih = (const float*)d_in[4];
    const float* W_hh = (const float*)d_in[5];
    const float* b_ih = (const float*)d_in[6];
    const float* b_hh = (const float*)d_in[7];
    const float* Wh1  = (const float*)d_in[8];
    const float* bh1  = (const float*)d_in[9];
    const float* Wh2  = (const float*)d_in[10];
    const float* bh2  = (const float*)d_in[11];
    const float* Wh3  = (const float*)d_in[12];
    const float* bh3  = (const float*)d_in[13];
    const float* Wh4  = (const float*)d_in[14];
    const float* bh4  = (const float*)d_in[15];
    float* out = (float*)d_out;

    cudaFuncSetAttribute(k_lstm, cudaFuncAttributeMaxDynamicSharedMemorySize, SMEML);

    // launches 1-5 so that k_lstm is launch #6 (ncu -s 5 -c 1 target)
    k_setup1<<<1, 512>>>(W1, W2);
    k_trans<<<dim3(16, 126), dim3(32, 8)>>>(W_ih, W_hh, b_ih, b_hh);
    k_tables<<<8, 256>>>();
    k_front<<<BB * TT, 128>>>(x, Ahat);
    k_zero<<<512, 256>>>();
    k_lstm<<<dim3(16, 8), 256, SMEML>>>();

    k_trh<<<(NR * HH + 255) / 256, 256>>>();
    k_gemmt<<<dim3(47, 8), 256>>>(0, Wh1, bh1, 1, NR, HH, M1, 1);
    k_gemmt<<<dim3(16, 8), 256>>>(1, Wh2, bh2, 2, NR, M1, M2, 1);
    k_gemmt<<<dim3(47, 8), 256>>>(2, Wh3, bh3, 3, NR, M2, M1, 1);
    k_final<<<NR, 256>>>(Wh4, bh4, out);
}

// round 12
// speedup vs baseline: 1.7959x; 1.3720x over previous
#include <cuda_runtime.h>
#include <cuda_bf16.h>
#include <math.h>

#define BB 4
#define TT 192
#define LL 120
#define GG 500
#define HH 500      // HL
#define H4 2000
#define H4P 2048
#define KPAD 520    // padded K (bf16 units); 1040B row stride -> LDSM conflict-free
#define NR 480
#define NRP 512
#define OD 24
#define M1 3000
#define M2 1000

// k_lstm tiling: 128 blocks = 16 col-tiles(128 gate-cols) x 8 row-tiles(64 rows)
#define LSW (128 * KPAD * 2)    // 133120 W stripe bytes (resident)
#define LSA (64 * KPAD * 2)     // 66560 h stripe bytes
#define SMEML (LSW + LSA + 32)

// ------------------------- scratch (device globals) -------------------------
__device__ float g_P[GG];
__device__ float g_Nv[GG];
__device__ float g_rho[GG];
__device__ float g_esign[GG];
__device__ int   g_ef[GG];
__device__ int   g_act0[GG];
__device__ int   g_nev[1];
__device__ __align__(16) float g_bias[H4P];                   // interleaved cq = hc*4+gate
__device__ __align__(16) float g_WihTp[GG * H4P];             // fp32 [f][cq]
__device__ __align__(16) float g_TAB[(GG + 1) * H4P * 2];     // [s][cq*2 + {A,B}]
__device__ __align__(16) unsigned short g_Whh[H4P * KPAD];    // bf16 W_hh [cq][k]
__device__ __align__(16) float4 g_uvs[TT * NRP];              // (u, v, seg-bits, 0)
__device__ __align__(16) unsigned short g_h3[3][NRP * KPAD];  // bf16 h ring [row][k]
__device__ __align__(16) float g_hF[HH * NRP];                // fp32 h_last [hc][row]
__device__ unsigned g_bar2[8][TT];                            // per-row-group barriers
__device__ __align__(16) float g_hT[NR * HH];
__device__ __align__(16) float g_z1[NR * M1];
__device__ __align__(16) float g_z2[NR * M2];
__device__ __align__(16) float g_z3[NR * M1];

// ------------------------- helpers -------------------------
__device__ __forceinline__ float fsig(float x) {
    return __fdividef(1.f, 1.f + __expf(-x));
}
__device__ __forceinline__ float ftanh(float x) {
    float ax = fabsf(x);
    float t  = __expf(-2.f * ax);
    float r  = __fdividef(1.f - t, 1.f + t);
    return copysignf(r, x);
}
__device__ __forceinline__ float tf32r(float x) {
    unsigned r;
    asm("cvt.rna.tf32.f32 %0, %1;" : "=r"(r) : "f"(x));
    return __uint_as_float(r);
}
__device__ __forceinline__ unsigned short f2bf(float v) {
    __nv_bfloat16 b = __float2bfloat16_rn(v);
    return *reinterpret_cast<unsigned short*>(&b);
}
__device__ __forceinline__ void mbar_init(unsigned a, unsigned c) {
    asm volatile("mbarrier.init.shared.b64 [%0], %1;" :: "r"(a), "r"(c) : "memory");
}
__device__ __forceinline__ void mbar_extx(unsigned a, unsigned tx) {
    asm volatile("mbarrier.arrive.expect_tx.shared.b64 _, [%0], %1;" :: "r"(a), "r"(tx) : "memory");
}
__device__ __forceinline__ void mbar_wait(unsigned a, unsigned ph) {
    asm volatile(
        "{\n\t.reg .pred P;\n"
        "W%=:\n\t"
        "mbarrier.try_wait.parity.acquire.cta.shared::cta.b64 P, [%0], %1, 0x989680;\n\t"
        "@P bra D%=;\n\t"
        "bra W%=;\n"
        "D%=:\n\t}"
        :: "r"(a), "r"(ph) : "memory");
}
__device__ __forceinline__ void bulkcp(unsigned dst, const void* src, unsigned bytes, unsigned mbar) {
    asm volatile(
        "cp.async.bulk.shared::cta.global.mbarrier::complete_tx::bytes [%0], [%1], %2, [%3];"
        :: "r"(dst), "l"(src), "r"(bytes), "r"(mbar) : "memory");
}
__device__ __forceinline__ void ldsm4(unsigned* r, unsigned addr) {
    asm volatile("ldmatrix.sync.aligned.m8n8.x4.shared.b16 {%0,%1,%2,%3}, [%4];"
                 : "=r"(r[0]), "=r"(r[1]), "=r"(r[2]), "=r"(r[3]) : "r"(addr));
}
__device__ __forceinline__ void mma16bf(float* d, const unsigned* a, const unsigned* b) {
    asm volatile(
        "mma.sync.aligned.m16n8k16.row.col.f32.bf16.bf16.f32 "
        "{%0,%1,%2,%3}, {%4,%5,%6,%7}, {%8,%9}, {%0,%1,%2,%3};"
        : "+f"(d[0]), "+f"(d[1]), "+f"(d[2]), "+f"(d[3])
        : "r"(a[0]), "r"(a[1]), "r"(a[2]), "r"(a[3]), "r"(b[0]), "r"(b[1]));
}
__device__ __forceinline__ void mma8(float* d, const unsigned* a, const unsigned* b) {
    asm volatile(
        "mma.sync.aligned.m16n8k8.row.col.f32.tf32.tf32.f32 "
        "{%0,%1,%2,%3}, {%4,%5,%6,%7}, {%8,%9}, {%0,%1,%2,%3};"
        : "+f"(d[0]), "+f"(d[1]), "+f"(d[2]), "+f"(d[3])
        : "r"(a[0]), "r"(a[1]), "r"(a[2]), "r"(a[3]), "r"(b[0]), "r"(b[1]));
}

// ------------------------- launch 1: P,N + breakpoint events (1 block) ------
__global__ void k_setup1(const float* __restrict__ W1, const float* __restrict__ W2) {
    __shared__ float srho[GG];
    __shared__ float ssg[GG];
    __shared__ int   sf[GG];
    __shared__ int   cnt;
    int tid = threadIdx.x;
    if (tid < GG) {
        float p = 0.f, n = 0.f;
        for (int g = 0; g < GG; g++) {
            float w = W1[g];
            float v = W2[g * GG + tid];
            p = fmaf(fmaxf(w, 0.f), v, p);
            n = fmaf(fmaxf(-w, 0.f), v, n);
        }
        g_P[tid]  = p;
        g_Nv[tid] = n;
    }
    if (tid == 0) cnt = 0;
    __syncthreads();
    if (tid < GG) {
        float p = g_P[tid], n = g_Nv[tid];
        int act0 = 0;
        float sgn = 0.f, rho = 0.f;
        if (n > 0.f) {
            if (p >= 0.f) { act0 = 1; }
            else { act0 = 0; rho = __fdividef(-p, n); sgn = 1.f; }
        } else if (n < 0.f) {
            if (p > 0.f) { act0 = 1; rho = __fdividef(p, -n); sgn = -1.f; }
            else { act0 = 0; }
        } else {
            act0 = (p > 0.f) ? 1 : 0;
        }
        g_act0[tid] = act0;
        if (sgn != 0.f) {
            int e = atomicAdd(&cnt, 1);
            srho[e] = rho; ssg[e] = sgn; sf[e] = tid;
        }
    }
    __syncthreads();
    int E = cnt;
    if (tid == 0) g_nev[0] = E;
    if (tid < E) {
        float r = srho[tid];
        int rank = 0;
        for (int j = 0; j < E; j++) {
            float rj = srho[j];
            rank += (rj < r) || (rj == r && j < tid);
        }
        g_rho[rank]   = r;
        g_esign[rank] = ssg[tid];
        g_ef[rank]    = sf[tid];
    }
}

// ------------------------- launch 2: weight reshuffles + bias ---------------
__global__ void k_trans(const float* __restrict__ W_ih, const float* __restrict__ W_hh,
                        const float* __restrict__ b_ih, const float* __restrict__ b_hh) {
    __shared__ float tle[32][33];
    int x = threadIdx.x, y = threadIdx.y;
    if (blockIdx.y < 63) {
        int f0 = blockIdx.x * 32;
        int h0 = blockIdx.y * 32;
        for (int i = y; i < 32; i += 8) {
            int h = h0 + i, f = f0 + x;
            tle[i][x] = (h < H4 && f < GG) ? W_ih[(size_t)h * GG + f] : 0.f;
        }
        __syncthreads();
        for (int i = y; i < 32; i += 8) {
            int f = f0 + i, h = h0 + x;
            if (f < GG && h < H4) {
                int cq = (h % HH) * 4 + h / HH;
                g_WihTp[(size_t)f * H4P + cq] = tle[x][i];
            }
        }
    } else {
        int r0 = (blockIdx.y - 63) * 32;
        int k0 = blockIdx.x * 32;
        for (int i = y; i < 32; i += 8) {
            int h = r0 + i;
            if (h < H4) {
                int cq = (h % HH) * 4 + h / HH;
                int k = k0 + x;
                g_Whh[(size_t)cq * KPAD + k] = (k < GG) ? f2bf(W_hh[(size_t)h * HH + k])
                                                        : (unsigned short)0;
            }
        }
        if (blockIdx.x == 0 && blockIdx.y == 125) {
            int tid = y * 32 + x;
            for (int h = tid; h < H4; h += 256) {
                int cq = (h % HH) * 4 + h / HH;
                g_bias[cq] = b_ih[h] + b_hh[h];
            }
        }
    }
}

// ------------------------- launch 3: interleaved segment tables -------------
__global__ void k_tables() {
    int cq = blockIdx.x * 256 + threadIdx.x;   // 0..2047
    float accA = 0.f, accB = 0.f;
    for (int f = 0; f < GG; f++) {
        if (g_act0[f]) {
            float w = g_WihTp[(size_t)f * H4P + cq];
            accA = fmaf(w, g_P[f],  accA);
            accB = fmaf(w, g_Nv[f], accB);
        }
    }
    g_TAB[(size_t)cq * 2]     = accA;
    g_TAB[(size_t)cq * 2 + 1] = accB;
    int E = g_nev[0];
    for (int e = 0; e < E; e++) {
        int f = g_ef[e];
        float w = g_WihTp[(size_t)f * H4P + cq] * g_esign[e];
        accA = fmaf(w, g_P[f],  accA);
        accB = fmaf(w, g_Nv[f], accB);
        size_t base = (size_t)(e + 1) * (H4P * 2) + (size_t)cq * 2;
        g_TAB[base]     = accA;
        g_TAB[base + 1] = accB;
    }
}

// ------------------------- launch 4: GCN front -> u,v,seg -------------------
// A_hat is symmetric -> read columns (coalesced across threads).
__global__ void k_front(const float* __restrict__ x, const float* __restrict__ Ahat) {
    __shared__ float xr[LL], sp[LL], sn[LL];
    int bid = blockIdx.x;
    int b = bid / TT, t = bid % TT;
    int tid = threadIdx.x;
    if (tid < LL) xr[tid] = x[(b * TT + t) * LL + tid];
    __syncthreads();
    if (tid < LL) {
        float s = 0.f;
        for (int l = 0; l < LL; l++) s = fmaf(Ahat[l * LL + tid], xr[l], s);
        sp[tid] = fmaxf(s, 0.f);
        sn[tid] = fmaxf(-s, 0.f);
    }
    __syncthreads();
    if (tid < LL) {
        float uu = 0.f, vv = 0.f;
        for (int l = 0; l < LL; l++) {
            float a = Ahat[l * LL + tid];
            uu = fmaf(a, sp[l], uu);
            vv = fmaf(a, sn[l], vv);
        }
        int E = g_nev[0];
        int s;
        if (uu > 0.f) {
            float rho = vv / uu;
            int lo = 0, hi = E;
            while (lo < hi) {
                int mid = (lo + hi) >> 1;
                if (g_rho[mid] < rho) lo = mid + 1; else hi = mid;
            }
            s = lo;
        } else {
            s = (vv > 0.f) ? E : 0;
        }
        g_uvs[t * NRP + b * LL + tid] = make_float4(uu, vv, __int_as_float(s), 0.f);
    }
}

// ------------------------- launch 5: per-replay zero init -------------------
__global__ void k_zero() {
    const size_t H3W  = 3ull * NRP * KPAD / 2;              // u32 words of h ring
    const size_t BARW = 8 * TT;
    const size_t UVSW = (size_t)TT * (NRP - NR);            // pad float4 slots
    const size_t TOTAL = H3W + BARW + UVSW;
    size_t stride = (size_t)gridDim.x * 256;
    for (size_t i = (size_t)blockIdx.x * 256 + threadIdx.x; i < TOTAL; i += stride) {
        if (i < H3W) {
            reinterpret_cast<unsigned*>(g_h3)[i] = 0u;
        } else if (i < H3W + BARW) {
            (&g_bar2[0][0])[i - H3W] = 0u;
        } else {
            size_t j = i - H3W - BARW;
            size_t t = j / (NRP - NR);
            size_t r = NR + j % (NRP - NR);
            g_uvs[t * NRP + r] = make_float4(0.f, 0.f, 0.f, 0.f);
        }
    }
}

// ------------------------- launch 6: persistent LSTM ------------------------
// 128 blocks = 16 ct (128 gate-cols) x 8 rt (64 rows). W_hh stripe resident.
// Warp tile 32 cols x 32 rows (4 col-groups x 2 row-groups). c in registers.
__global__ __launch_bounds__(256) void k_lstm() {
    extern __shared__ __align__(16) char smc[];
    unsigned smb = (unsigned)__cvta_generic_to_shared(smc);
    unsigned sWb = smb, sAb = smb + LSW, mbH = smb + LSW + LSA, mbW = mbH + 8;
    int tid = threadIdx.x, warp = tid >> 5, lane = tid & 31;
    int g = lane >> 2, tg = lane & 3;
    int ct = blockIdx.x, rt = blockIdx.y;
    int R0 = rt * 64;
    int cwarp = warp & 3, rwarp = warp >> 2;
    int CW0 = ct * 128 + cwarp * 32;
    int RW0 = R0 + rwarp * 32;

    if (tid == 0) { mbar_init(mbH, 1); mbar_init(mbW, 1); }
    __syncthreads();
    if (tid == 0) {
        mbar_extx(mbW, LSW);
        const char* wsrc = (const char*)(g_Whh + (size_t)ct * 128 * KPAD);
        bulkcp(sWb, wsrc, LSW / 2, mbW);
        bulkcp(sWb + LSW / 2, wsrc + LSW / 2, LSW / 2, mbW);
    }

    // ldsm addresses
    int arow = (lane & 7) + ((lane >> 3) & 1) * 8;
    unsigned akB = ((lane >> 4) & 1) * 16;
    unsigned aAdr[2];
    #pragma unroll
    for (int mi = 0; mi < 2; mi++)
        aAdr[mi] = sAb + (unsigned)((rwarp * 32 + mi * 16 + arow) * (KPAD * 2)) + akB;
    int wn0 = cwarp * 32 + (lane & 7) + ((lane >> 4) & 1) * 8;
    unsigned wkB = ((lane >> 3) & 1) * 16;
    unsigned wAdr0 = sWb + (unsigned)(wn0 * (KPAD * 2)) + wkB;
    unsigned wAdr1 = wAdr0 + 16u * (KPAD * 2);

    int cA0 = CW0 + 2 * tg;
    float2 bi[4];
    #pragma unroll
    for (int ni = 0; ni < 4; ni++) bi[ni] = *(const float2*)&g_bias[cA0 + ni * 8];

    // persistent c registers + epilogue coordinates
    float creg[2][4];
    #pragma unroll
    for (int mi = 0; mi < 2; mi++)
        #pragma unroll
        for (int ni = 0; ni < 4; ni++) creg[mi][ni] = 0.f;
    int par = lane & 1;
    int hcb = (CW0 >> 2) + (tg >> 1);         // + ni*2
    int rowb = RW0 + g + par * 8;             // + mi*16

    float d[2][4][4], dn[2][4][4];

    // prologue for step t (reads static uvs/TAB only)
    auto prologue = [&](int t, float (&dd)[2][4][4]) {
        #pragma unroll
        for (int mi = 0; mi < 2; mi++) {
            int rA = RW0 + mi * 16 + g;
            float4 pa = g_uvs[t * NRP + rA];
            float4 pb = g_uvs[t * NRP + rA + 8];
            const float4* TA = (const float4*)&g_TAB[(size_t)__float_as_int(pa.z) * (H4P * 2)];
            const float4* TB = (const float4*)&g_TAB[(size_t)__float_as_int(pb.z) * (H4P * 2)];
            #pragma unroll
            for (int ni = 0; ni < 4; ni++) {
                int c = cA0 + ni * 8;
                float4 qa = TA[c >> 1];
                float4 qb = TB[c >> 1];
                dd[mi][ni][0] = fmaf(pa.x, qa.x, fmaf(pa.y, qa.y, bi[ni].x));
                dd[mi][ni][1] = fmaf(pa.x, qa.z, fmaf(pa.y, qa.w, bi[ni].y));
                dd[mi][ni][2] = fmaf(pb.x, qb.x, fmaf(pb.y, qb.y, bi[ni].x));
                dd[mi][ni][3] = fmaf(pb.x, qb.z, fmaf(pb.y, qb.w, bi[ni].y));
            }
        }
    };

    prologue(0, d);
    mbar_wait(mbW, 0);

    #pragma unroll 1
    for (int t = 0; t < TT; t++) {
        const unsigned short* hin = g_h3[(t + 2) % 3];
        unsigned short* hout = g_h3[t % 3];
        if (tid == 0) {
            mbar_extx(mbH, LSA);
            const char* src = (const char*)(hin + (size_t)R0 * KPAD);
            bulkcp(sAb, src, LSA / 2, mbH);
            bulkcp(sAb + LSA / 2, src + LSA / 2, LSA / 2, mbH);
        }
        mbar_wait(mbH, t & 1);

        #pragma unroll 4
        for (int c16 = 0; c16 < 32; c16++) {
            unsigned kB = (unsigned)(c16 * 32);
            unsigned b8[8], a[2][4];
            ldsm4(b8,     wAdr0 + kB);
            ldsm4(b8 + 4, wAdr1 + kB);
            ldsm4(a[0], aAdr[0] + kB);
            ldsm4(a[1], aAdr[1] + kB);
            #pragma unroll
            for (int mi = 0; mi < 2; mi++) {
                mma16bf(d[mi][0], a[mi], b8);
                mma16bf(d[mi][1], a[mi], b8 + 2);
                mma16bf(d[mi][2], a[mi], b8 + 4);
                mma16bf(d[mi][3], a[mi], b8 + 6);
            }
        }

        // epilogue: lane-split (even lane -> row rA, odd lane -> row rB)
        int last = (t == TT - 1);
        #pragma unroll
        for (int mi = 0; mi < 2; mi++) {
            #pragma unroll
            for (int ni = 0; ni < 4; ni++) {
                float d0 = d[mi][ni][0], d1 = d[mi][ni][1];
                float d2 = d[mi][ni][2], d3 = d[mi][ni][3];
                float e0 = __shfl_xor_sync(0xffffffffu, d0, 1);
                float e1 = __shfl_xor_sync(0xffffffffu, d1, 1);
                float e2 = __shfl_xor_sync(0xffffffffu, d2, 1);
                float e3 = __shfl_xor_sync(0xffffffffu, d3, 1);
                float iv = par ? e2 : d0;
                float fv = par ? e3 : d1;
                float gv = par ? d2 : e0;
                float ov = par ? d3 : e1;
                float cn = fmaf(fsig(fv), creg[mi][ni], fsig(iv) * ftanh(gv));
                creg[mi][ni] = cn;
                float hv = fsig(ov) * ftanh(cn);
                int hc = hcb + ni * 2;
                int row = rowb + mi * 16;
                if (hc < HH) {
                    hout[(size_t)row * KPAD + hc] = f2bf(hv);
                    if (last) g_hF[hc * NRP + row] = hv;
                }
            }
        }

        // row-group barrier (16 blocks); prefetch next prologue while waiting
        __threadfence();
        __syncthreads();
        if (tid == 0) atomicAdd(&g_bar2[rt][t], 1u);
        if (t + 1 < TT) prologue(t + 1, dn);
        if (tid == 0) {
            while (*(volatile unsigned*)&g_bar2[rt][t] < 16u) {}
        }
        __syncthreads();
        __threadfence();
        #pragma unroll
        for (int mi = 0; mi < 2; mi++)
            #pragma unroll
            for (int ni = 0; ni < 4; ni++)
                #pragma unroll
                for (int q = 0; q < 4; q++) d[mi][ni][q] = dn[mi][ni][q];
    }
}

// ------------------------- h_last transpose -------------------------
__global__ void k_trh() {
    int idx = blockIdx.x * 256 + threadIdx.x;
    if (idx >= NR * HH) return;
    int n = idx / HH, k = idx % HH;
    g_hT[idx] = g_hF[k * NRP + n];
}

// ------------------------- tf32 MMA GEMM: C = act(A @ W + b) ----------------
__device__ __forceinline__ float* selbuf(int s) {
    switch (s) {
        case 0: return g_hT;
        case 1: return g_z1;
        case 2: return g_z2;
        default: return g_z3;
    }
}

__global__ __launch_bounds__(256) void k_gemmt(int aSel, const float* __restrict__ W,
                                               const float* __restrict__ bias, int cSel,
                                               int M, int K, int N, int doRelu) {
    const float* A = selbuf(aSel);
    float* C = selbuf(cSel);
    __shared__ __align__(16) float As[64 * 36];
    __shared__ __align__(16) float Ws[32 * 72];
    int tid  = threadIdx.x;
    int warp = tid >> 5;
    int lane = tid & 31;
    int g  = lane >> 2;
    int tg = lane & 3;
    int n0 = blockIdx.x * 64, m0 = blockIdx.y * 64;
    int wm = (warp >> 2) * 32;
    int wn = (warp & 3) * 16;

    int ami = tid >> 2;
    int akq = (tid & 3) * 8;
    int wkk = tid >> 3;
    int wnq = (tid & 7) * 8;

    float d[2][2][4];
    #pragma unroll
    for (int i = 0; i < 2; i++)
        #pragma unroll
        for (int j = 0; j < 2; j++)
            #pragma unroll
            for (int q = 0; q < 4; q++) d[i][j][q] = 0.f;

    int nslab = (K + 31) / 32;
    float rA[8], rW[8];

    {
        int m = m0 + ami;
        #pragma unroll
        for (int j = 0; j < 8; j++) {
            int k = akq + j;
            rA[j] = (m < M && k < K) ? A[(size_t)m * K + k] : 0.f;
        }
        #pragma unroll
        for (int j = 0; j < 8; j++) {
            int n = n0 + wnq + j;
            rW[j] = (wkk < K && n < N) ? W[(size_t)wkk * N + n] : 0.f;
        }
    }

    #pragma unroll 1
    for (int s = 0; s < nslab; s++) {
        #pragma unroll
        for (int j = 0; j < 8; j++) As[ami * 36 + akq + j] = tf32r(rA[j]);
        #pragma unroll
        for (int j = 0; j < 8; j++) Ws[wkk * 72 + wnq + j] = tf32r(rW[j]);
        __syncthreads();
        if (s + 1 < nslab) {
            int k0 = (s + 1) * 32;
            int m = m0 + ami;
            #pragma unroll
            for (int j = 0; j < 8; j++) {
                int k = k0 + akq + j;
                rA[j] = (m < M && k < K) ? A[(size_t)m * K + k] : 0.f;
            }
            #pragma unroll
            for (int j = 0; j < 8; j++) {
                int k = k0 + wkk;
                int n = n0 + wnq + j;
                rW[j] = (k < K && n < N) ? W[(size_t)k * N + n] : 0.f;
            }
        }
        const unsigned* Asu = reinterpret_cast<const unsigned*>(As);
        const unsigned* Wsu = reinterpret_cast<const unsigned*>(Ws);
        #pragma unroll
        for (int c8 = 0; c8 < 4; c8++) {
            int kc = c8 * 8;
            unsigned a[2][4], b[2][2];
            #pragma unroll
            for (int mi = 0; mi < 2; mi++) {
                int mbase = (wm + mi * 16 + g) * 36 + kc;
                a[mi][0] = Asu[mbase + tg];
                a[mi][1] = Asu[mbase + 8 * 36 + tg];
                a[mi][2] = Asu[mbase + tg + 4];
                a[mi][3] = Asu[mbase + 8 * 36 + tg + 4];
            }
            #pragma unroll
            for (int ni = 0; ni < 2; ni++) {
                int nb = wn + ni * 8 + g;
                b[ni][0] = Wsu[(kc + tg) * 72 + nb];
                b[ni][1] = Wsu[(kc + tg + 4) * 72 + nb];
            }
            #pragma unroll
            for (int mi = 0; mi < 2; mi++)
                #pragma unroll
                for (int ni = 0; ni < 2; ni++)
                    mma8(d[mi][ni], a[mi], b[ni]);
        }
        __syncthreads();
    }

    #pragma unroll
    for (int mi = 0; mi < 2; mi++) {
        #pragma unroll
        for (int ni = 0; ni < 2; ni++) {
            int mA = m0 + wm + mi * 16 + g;
            int mB = mA + 8;
            int n  = n0 + wn + ni * 8 + 2 * tg;
            float b0 = (n < N)     ? bias[n]     : 0.f;
            float b1 = (n + 1 < N) ? bias[n + 1] : 0.f;
            float v;
            if (mA < M) {
                if (n < N) {
                    v = d[mi][ni][0] + b0;
                    C[(size_t)mA * N + n] = doRelu ? fmaxf(v, 0.f) : v;
                }
                if (n + 1 < N) {
                    v = d[mi][ni][1] + b1;
                    C[(size_t)mA * N + n + 1] = doRelu ? fmaxf(v, 0.f) : v;
                }
            }
            if (mB < M) {
                if (n < N) {
                    v = d[mi][ni][2] + b0;
                    C[(size_t)mB * N + n] = doRelu ? fmaxf(v, 0.f) : v;
                }
                if (n + 1 < N) {
                    v = d[mi][ni][3] + b1;
                    C[(size_t)mB * N + n + 1] = doRelu ? fmaxf(v, 0.f) : v;
                }
            }
        }
    }
}

// ------------------------- final layer -------------------------
__global__ void k_final(const float* __restrict__ Wh4, const float* __restrict__ bh4,
                        float* __restrict__ out) {
    __shared__ float zs[M1];
    int n = blockIdx.x;
    int tid = threadIdx.x;
    for (int k = tid; k < M1; k += 256) zs[k] = g_z3[n * M1 + k];
    __syncthreads();
    int w = tid >> 5, lane = tid & 31;
    #pragma unroll
    for (int oi = 0; oi < 3; oi++) {
        int o = w + oi * 8;
        float p = 0.f;
        for (int k = lane; k < M1; k += 32) p = fmaf(zs[k], Wh4[k * OD + o], p);
        #pragma unroll
        for (int off = 16; off; off >>= 1) p += __shfl_down_sync(0xffffffffu, p, off);
        if (lane == 0) {
            float y = fsig(p + bh4[o]);
            int b = n / LL, l = n % LL;
            out[(b * OD + o) * LL + l] = y;
        }
    }
}

// ------------------------- launcher -------------------------
extern "C" void kernel_launch(void* const* d_in, const int* in_sizes, int n_in,
                              void* d_out, int out_size) {
    const float* x    = (const float*)d_in[0];
    const float* Ahat = (const float*)d_in[1];
    const float* W1   = (const float*)d_in[2];
    const float* W2   = (const float*)d_in[3];
    const float* W_ih = (const float*)d_in[4];
    const float* W_hh = (const float*)d_in[5];
    const float* b_ih = (const float*)d_in[6];
    const float* b_hh = (const float*)d_in[7];
    const float* Wh1  = (const float*)d_in[8];
    const float* bh1  = (const float*)d_in[9];
    const float* Wh2  = (const float*)d_in[10];
    const float* bh2  = (const float*)d_in[11];
    const float* Wh3  = (const float*)d_in[12];
    const float* bh3  = (const float*)d_in[13];
    const float* Wh4  = (const float*)d_in[14];
    const float* bh4  = (const float*)d_in[15];
    float* out = (float*)d_out;

    cudaFuncSetAttribute(k_lstm, cudaFuncAttributeMaxDynamicSharedMemorySize, SMEML);

    // launches 1-5 so that k_lstm is launch #6 (ncu -s 5 -c 1 target)
    k_setup1<<<1, 512>>>(W1, W2);
    k_trans<<<dim3(16, 126), dim3(32, 8)>>>(W_ih, W_hh, b_ih, b_hh);
    k_tables<<<8, 256>>>();
    k_front<<<BB * TT, 128>>>(x, Ahat);
    k_zero<<<512, 256>>>();
    k_lstm<<<dim3(16, 8), 256, SMEML>>>();

    k_trh<<<(NR * HH + 255) / 256, 256>>>();
    k_gemmt<<<dim3(47, 8), 256>>>(0, Wh1, bh1, 1, NR, HH, M1, 1);
    k_gemmt<<<dim3(16, 8), 256>>>(1, Wh2, bh2, 2, NR, M1, M2, 1);
    k_gemmt<<<dim3(47, 8), 256>>>(2, Wh3, bh3, 3, NR, M2, M1, 1);
    k_final<<<NR, 256>>>(Wh4, bh4, out);
}

// round 14
// speedup vs baseline: 1.8780x; 1.0457x over previous
#include <cuda_runtime.h>
#include <cuda_bf16.h>
#include <math.h>

#define BB 4
#define TT 192
#define LL 120
#define GG 500
#define HH 500      // HL
#define H4 2000
#define H4P 2048
#define KPAD 520    // padded K (bf16 units); 1040B row stride -> LDSM conflict-free
#define NR 480
#define NRP 512
#define OD 24
#define M1 3000
#define M2 1000

// k_lstm tiling: 128 blocks = 16 col-tiles(128 gate-cols) x 8 row-tiles(64 rows)
#define LSW (128 * KPAD * 2)    // 133120 W stripe bytes (resident)
#define LSA (64 * KPAD * 2)     // 66560 h stripe bytes
#define SMEML (LSW + LSA + 32)

// ------------------------- scratch (device globals) -------------------------
__device__ float g_Ppart[8][512];
__device__ float g_Npart[8][512];
__device__ float g_P[GG];
__device__ float g_Nv[GG];
__device__ float g_rho[GG];
__device__ float g_esign[GG];
__device__ int   g_ef[GG];
__device__ int   g_act0[GG];
__device__ int   g_nev[1];
__device__ __align__(16) float g_bias[H4P];                   // interleaved cq = hc*4+gate
__device__ __align__(16) float g_WihTp[GG * H4P];             // fp32 [f][cq]
__device__ __align__(16) float g_TAB[(GG + 1) * H4P * 2];     // [s][cq*2 + {A,B}]
__device__ __align__(16) unsigned short g_Whh[H4P * KPAD];    // bf16 W_hh [cq][k]
__device__ __align__(16) float4 g_uvs[TT * NRP];              // (u, v, seg-bits, 0)
__device__ __align__(16) unsigned short g_h3[3][NRP * KPAD];  // bf16 h ring [row][k]
__device__ __align__(16) float g_hF[HH * NRP];                // fp32 h_last [hc][row]
__device__ unsigned g_bar2[8][TT];                            // per-row-group barriers
__device__ __align__(16) float g_hT[NR * HH];
__device__ __align__(16) float g_z1[NR * M1];
__device__ __align__(16) float g_z2[NR * M2];
__device__ __align__(16) float g_z3[NR * M1];

// ------------------------- helpers -------------------------
__device__ __forceinline__ float fsig(float x) {
    return __fdividef(1.f, 1.f + __expf(-x));
}
__device__ __forceinline__ float ftanh(float x) {
    float ax = fabsf(x);
    float t  = __expf(-2.f * ax);
    float r  = __fdividef(1.f - t, 1.f + t);
    return copysignf(r, x);
}
__device__ __forceinline__ float tf32r(float x) {
    unsigned r;
    asm("cvt.rna.tf32.f32 %0, %1;" : "=r"(r) : "f"(x));
    return __uint_as_float(r);
}
__device__ __forceinline__ unsigned short f2bf(float v) {
    __nv_bfloat16 b = __float2bfloat16_rn(v);
    return *reinterpret_cast<unsigned short*>(&b);
}
__device__ __forceinline__ void mbar_init(unsigned a, unsigned c) {
    asm volatile("mbarrier.init.shared.b64 [%0], %1;" :: "r"(a), "r"(c) : "memory");
}
__device__ __forceinline__ void mbar_extx(unsigned a, unsigned tx) {
    asm volatile("mbarrier.arrive.expect_tx.shared.b64 _, [%0], %1;" :: "r"(a), "r"(tx) : "memory");
}
__device__ __forceinline__ void mbar_wait(unsigned a, unsigned ph) {
    asm volatile(
        "{\n\t.reg .pred P;\n"
        "W%=:\n\t"
        "mbarrier.try_wait.parity.acquire.cta.shared::cta.b64 P, [%0], %1, 0x989680;\n\t"
        "@P bra D%=;\n\t"
        "bra W%=;\n"
        "D%=:\n\t}"
        :: "r"(a), "r"(ph) : "memory");
}
__device__ __forceinline__ void bulkcp(unsigned dst, const void* src, unsigned bytes, unsigned mbar) {
    asm volatile(
        "cp.async.bulk.shared::cta.global.mbarrier::complete_tx::bytes [%0], [%1], %2, [%3];"
        :: "r"(dst), "l"(src), "r"(bytes), "r"(mbar) : "memory");
}
__device__ __forceinline__ void ldsm4(unsigned* r, unsigned addr) {
    asm volatile("ldmatrix.sync.aligned.m8n8.x4.shared.b16 {%0,%1,%2,%3}, [%4];"
                 : "=r"(r[0]), "=r"(r[1]), "=r"(r[2]), "=r"(r[3]) : "r"(addr));
}
__device__ __forceinline__ void mma16bf(float* d, const unsigned* a, const unsigned* b) {
    asm volatile(
        "mma.sync.aligned.m16n8k16.row.col.f32.bf16.bf16.f32 "
        "{%0,%1,%2,%3}, {%4,%5,%6,%7}, {%8,%9}, {%0,%1,%2,%3};"
        : "+f"(d[0]), "+f"(d[1]), "+f"(d[2]), "+f"(d[3])
        : "r"(a[0]), "r"(a[1]), "r"(a[2]), "r"(a[3]), "r"(b[0]), "r"(b[1]));
}
__device__ __forceinline__ void mma8(float* d, const unsigned* a, const unsigned* b) {
    asm volatile(
        "mma.sync.aligned.m16n8k8.row.col.f32.tf32.tf32.f32 "
        "{%0,%1,%2,%3}, {%4,%5,%6,%7}, {%8,%9}, {%0,%1,%2,%3};"
        : "+f"(d[0]), "+f"(d[1]), "+f"(d[2]), "+f"(d[3])
        : "r"(a[0]), "r"(a[1]), "r"(a[2]), "r"(a[3]), "r"(b[0]), "r"(b[1]));
}

// ------------------------- launch 1: weight reshuffles + bias + P,N partials
// grid (16,127): y<63 -> WihTp transpose tiles; y in [63,126) -> Whh bf16 rows
// (+bias on one block); y==126 -> P,N partial scans (16 blocks, 8 g-ranges).
__global__ void k_trans(const float* __restrict__ W_ih, const float* __restrict__ W_hh,
                        const float* __restrict__ b_ih, const float* __restrict__ b_hh,
                        const float* __restrict__ W1, const float* __restrict__ b_W2) {
    __shared__ float tle[32][33];
    int x = threadIdx.x, y = threadIdx.y;
    if (blockIdx.y < 63) {
        int f0 = blockIdx.x * 32;
        int h0 = blockIdx.y * 32;
        for (int i = y; i < 32; i += 8) {
            int h = h0 + i, f = f0 + x;
            tle[i][x] = (h < H4 && f < GG) ? W_ih[(size_t)h * GG + f] : 0.f;
        }
        __syncthreads();
        for (int i = y; i < 32; i += 8) {
            int f = f0 + i, h = h0 + x;
            if (f < GG && h < H4) {
                int cq = (h % HH) * 4 + h / HH;
                g_WihTp[(size_t)f * H4P + cq] = tle[x][i];
            }
        }
    } else if (blockIdx.y < 126) {
        int r0 = (blockIdx.y - 63) * 32;
        int k0 = blockIdx.x * 32;
        for (int i = y; i < 32; i += 8) {
            int h = r0 + i;
            if (h < H4) {
                int cq = (h % HH) * 4 + h / HH;
                int k = k0 + x;
                g_Whh[(size_t)cq * KPAD + k] = (k < GG) ? f2bf(W_hh[(size_t)h * HH + k])
                                                        : (unsigned short)0;
            }
        }
        if (blockIdx.x == 0 && blockIdx.y == 125) {
            int tid = y * 32 + x;
            for (int h = tid; h < H4; h += 256) {
                int cq = (h % HH) * 4 + h / HH;
                g_bias[cq] = b_ih[h] + b_hh[h];
            }
        }
    } else {
        // P,N partials: part = bx/2 covers g in [63*part, min(63*part+63, 500))
        int tid = y * 32 + x;
        int part = blockIdx.x >> 1;
        int f = (blockIdx.x & 1) * 256 + tid;
        int g0 = part * 63;
        int g1 = min(g0 + 63, GG);
        float p = 0.f, n = 0.f;
        if (f < GG) {
            for (int g = g0; g < g1; g++) {
                float w = W1[g];
                float v = b_W2[(size_t)g * GG + f];
                p = fmaf(fmaxf(w, 0.f), v, p);
                n = fmaf(fmaxf(-w, 0.f), v, n);
            }
        }
        if (f < 512) {
            g_Ppart[part][f] = p;
            g_Npart[part][f] = n;
        }
    }
}

// ------------------------- launch 2: reduce P,N + breakpoint events ---------
// All __syncthreads at top level; work predicated on tid.
__global__ void k_events() {
    __shared__ float srho[GG];
    __shared__ float ssg[GG];
    __shared__ int   sf[GG];
    __shared__ int   cnt;
    int tid = threadIdx.x;
    if (tid == 0) cnt = 0;
    float p = 0.f, n = 0.f;
    if (tid < GG) {
        #pragma unroll
        for (int part = 0; part < 8; part++) {
            p += g_Ppart[part][tid];
            n += g_Npart[part][tid];
        }
        g_P[tid]  = p;
        g_Nv[tid] = n;
    }
    __syncthreads();
    if (tid < GG) {
        int act0 = 0;
        float sgn = 0.f, rho = 0.f;
        if (n > 0.f) {
            if (p >= 0.f) { act0 = 1; }
            else { act0 = 0; rho = __fdividef(-p, n); sgn = 1.f; }
        } else if (n < 0.f) {
            if (p > 0.f) { act0 = 1; rho = __fdividef(p, -n); sgn = -1.f; }
            else { act0 = 0; }
        } else {
            act0 = (p > 0.f) ? 1 : 0;
        }
        g_act0[tid] = act0;
        if (sgn != 0.f) {
            int e = atomicAdd(&cnt, 1);
            srho[e] = rho; ssg[e] = sgn; sf[e] = tid;
        }
    }
    __syncthreads();
    int E = cnt;
    if (tid == 0) g_nev[0] = E;
    if (tid < E) {
        float r = srho[tid];
        int rank = 0;
        for (int j = 0; j < E; j++) {
            float rj = srho[j];
            rank += (rj < r) || (rj == r && j < tid);
        }
        g_rho[rank]   = r;
        g_esign[rank] = ssg[tid];
        g_ef[rank]    = sf[tid];
    }
}

// ------------------------- launch 3: interleaved segment tables -------------
__global__ void k_tables() {
    int cq = blockIdx.x * 256 + threadIdx.x;   // 0..2047
    float accA = 0.f, accB = 0.f;
    for (int f = 0; f < GG; f++) {
        if (g_act0[f]) {
            float w = g_WihTp[(size_t)f * H4P + cq];
            accA = fmaf(w, g_P[f],  accA);
            accB = fmaf(w, g_Nv[f], accB);
        }
    }
    g_TAB[(size_t)cq * 2]     = accA;
    g_TAB[(size_t)cq * 2 + 1] = accB;
    int E = g_nev[0];
    for (int e = 0; e < E; e++) {
        int f = g_ef[e];
        float w = g_WihTp[(size_t)f * H4P + cq] * g_esign[e];
        accA = fmaf(w, g_P[f],  accA);
        accB = fmaf(w, g_Nv[f], accB);
        size_t base = (size_t)(e + 1) * (H4P * 2) + (size_t)cq * 2;
        g_TAB[base]     = accA;
        g_TAB[base + 1] = accB;
    }
}

// ------------------------- launch 4: GCN front -> u,v,seg -------------------
// A_hat is symmetric -> read columns (coalesced across threads).
__global__ void k_front(const float* __restrict__ x, const float* __restrict__ Ahat) {
    __shared__ float xr[LL], sp[LL], sn[LL];
    int bid = blockIdx.x;
    int b = bid / TT, t = bid % TT;
    int tid = threadIdx.x;
    if (tid < LL) xr[tid] = x[(b * TT + t) * LL + tid];
    __syncthreads();
    if (tid < LL) {
        float s = 0.f;
        for (int l = 0; l < LL; l++) s = fmaf(Ahat[l * LL + tid], xr[l], s);
        sp[tid] = fmaxf(s, 0.f);
        sn[tid] = fmaxf(-s, 0.f);
    }
    __syncthreads();
    if (tid < LL) {
        float uu = 0.f, vv = 0.f;
        for (int l = 0; l < LL; l++) {
            float a = Ahat[l * LL + tid];
            uu = fmaf(a, sp[l], uu);
            vv = fmaf(a, sn[l], vv);
        }
        int E = g_nev[0];
        int s;
        if (uu > 0.f) {
            float rho = vv / uu;
            int lo = 0, hi = E;
            while (lo < hi) {
                int mid = (lo + hi) >> 1;
                if (g_rho[mid] < rho) lo = mid + 1; else hi = mid;
            }
            s = lo;
        } else {
            s = (vv > 0.f) ? E : 0;
        }
        g_uvs[t * NRP + b * LL + tid] = make_float4(uu, vv, __int_as_float(s), 0.f);
    }
}

// ------------------------- launch 5: per-replay zero init -------------------
__global__ void k_zero() {
    const size_t H3W  = 3ull * NRP * KPAD / 2;              // u32 words of h ring
    const size_t BARW = 8 * TT;
    const size_t UVSW = (size_t)TT * (NRP - NR);            // pad float4 slots
    const size_t TOTAL = H3W + BARW + UVSW;
    size_t stride = (size_t)gridDim.x * 256;
    for (size_t i = (size_t)blockIdx.x * 256 + threadIdx.x; i < TOTAL; i += stride) {
        if (i < H3W) {
            reinterpret_cast<unsigned*>(g_h3)[i] = 0u;
        } else if (i < H3W + BARW) {
            (&g_bar2[0][0])[i - H3W] = 0u;
        } else {
            size_t j = i - H3W - BARW;
            size_t t = j / (NRP - NR);
            size_t r = NR + j % (NRP - NR);
            g_uvs[t * NRP + r] = make_float4(0.f, 0.f, 0.f, 0.f);
        }
    }
}

// ------------------------- launch 6: persistent LSTM ------------------------
// 128 blocks = 16 ct (128 gate-cols) x 8 rt (64 rows). W_hh stripe resident.
// Warp tile 32 cols x 32 rows. c in registers. tid0-only fences in barrier.
__global__ __launch_bounds__(256) void k_lstm() {
    extern __shared__ __align__(16) char smc[];
    unsigned smb = (unsigned)__cvta_generic_to_shared(smc);
    unsigned sWb = smb, sAb = smb + LSW, mbH = smb + LSW + LSA, mbW = mbH + 8;
    int tid = threadIdx.x, warp = tid >> 5, lane = tid & 31;
    int g = lane >> 2, tg = lane & 3;
    int ct = blockIdx.x, rt = blockIdx.y;
    int R0 = rt * 64;
    int cwarp = warp & 3, rwarp = warp >> 2;
    int CW0 = ct * 128 + cwarp * 32;
    int RW0 = R0 + rwarp * 32;

    if (tid == 0) { mbar_init(mbH, 1); mbar_init(mbW, 1); }
    __syncthreads();
    if (tid == 0) {
        mbar_extx(mbW, LSW);
        const char* wsrc = (const char*)(g_Whh + (size_t)ct * 128 * KPAD);
        bulkcp(sWb, wsrc, LSW / 2, mbW);
        bulkcp(sWb + LSW / 2, wsrc + LSW / 2, LSW / 2, mbW);
    }

    // ldsm addresses
    int arow = (lane & 7) + ((lane >> 3) & 1) * 8;
    unsigned akB = ((lane >> 4) & 1) * 16;
    unsigned aAdr[2];
    #pragma unroll
    for (int mi = 0; mi < 2; mi++)
        aAdr[mi] = sAb + (unsigned)((rwarp * 32 + mi * 16 + arow) * (KPAD * 2)) + akB;
    int wn0 = cwarp * 32 + (lane & 7) + ((lane >> 4) & 1) * 8;
    unsigned wkB = ((lane >> 3) & 1) * 16;
    unsigned wAdr0 = sWb + (unsigned)(wn0 * (KPAD * 2)) + wkB;
    unsigned wAdr1 = wAdr0 + 16u * (KPAD * 2);

    int cA0 = CW0 + 2 * tg;
    float2 bi[4];
    #pragma unroll
    for (int ni = 0; ni < 4; ni++) bi[ni] = *(const float2*)&g_bias[cA0 + ni * 8];

    // persistent c registers + epilogue coordinates
    float creg[2][4];
    #pragma unroll
    for (int mi = 0; mi < 2; mi++)
        #pragma unroll
        for (int ni = 0; ni < 4; ni++) creg[mi][ni] = 0.f;
    int par = lane & 1;
    int hcb = (CW0 >> 2) + (tg >> 1);
    int rowb = RW0 + g + par * 8;

    float d[2][4][4], dn[2][4][4];

    auto prologue = [&](int t, float (&dd)[2][4][4]) {
        #pragma unroll
        for (int mi = 0; mi < 2; mi++) {
            int rA = RW0 + mi * 16 + g;
            float4 pa = g_uvs[t * NRP + rA];
            float4 pb = g_uvs[t * NRP + rA + 8];
            const float4* TA = (const float4*)&g_TAB[(size_t)__float_as_int(pa.z) * (H4P * 2)];
            const float4* TB = (const float4*)&g_TAB[(size_t)__float_as_int(pb.z) * (H4P * 2)];
            #pragma unroll
            for (int ni = 0; ni < 4; ni++) {
                int c = cA0 + ni * 8;
                float4 qa = TA[c >> 1];
                float4 qb = TB[c >> 1];
                dd[mi][ni][0] = fmaf(pa.x, qa.x, fmaf(pa.y, qa.y, bi[ni].x));
                dd[mi][ni][1] = fmaf(pa.x, qa.z, fmaf(pa.y, qa.w, bi[ni].y));
                dd[mi][ni][2] = fmaf(pb.x, qb.x, fmaf(pb.y, qb.y, bi[ni].x));
                dd[mi][ni][3] = fmaf(pb.x, qb.z, fmaf(pb.y, qb.w, bi[ni].y));
            }
        }
    };

    prologue(0, d);
    mbar_wait(mbW, 0);

    #pragma unroll 1
    for (int t = 0; t < TT; t++) {
        const unsigned short* hin = g_h3[(t + 2) % 3];
        unsigned short* hout = g_h3[t % 3];
        if (tid == 0) {
            mbar_extx(mbH, LSA);
            const char* src = (const char*)(hin + (size_t)R0 * KPAD);
            bulkcp(sAb, src, LSA / 2, mbH);
            bulkcp(sAb + LSA / 2, src + LSA / 2, LSA / 2, mbH);
        }
        mbar_wait(mbH, t & 1);

        #pragma unroll 4
        for (int c16 = 0; c16 < 32; c16++) {
            unsigned kB = (unsigned)(c16 * 32);
            unsigned b8[8], a[2][4];
            ldsm4(b8,     wAdr0 + kB);
            ldsm4(b8 + 4, wAdr1 + kB);
            ldsm4(a[0], aAdr[0] + kB);
            ldsm4(a[1], aAdr[1] + kB);
            #pragma unroll
            for (int mi = 0; mi < 2; mi++) {
                mma16bf(d[mi][0], a[mi], b8);
                mma16bf(d[mi][1], a[mi], b8 + 2);
                mma16bf(d[mi][2], a[mi], b8 + 4);
                mma16bf(d[mi][3], a[mi], b8 + 6);
            }
        }

        // epilogue: lane-split (even lane -> row rA, odd lane -> row rB)
        int last = (t == TT - 1);
        #pragma unroll
        for (int mi = 0; mi < 2; mi++) {
            #pragma unroll
            for (int ni = 0; ni < 4; ni++) {
                float d0 = d[mi][ni][0], d1 = d[mi][ni][1];
                float d2 = d[mi][ni][2], d3 = d[mi][ni][3];
                float e0 = __shfl_xor_sync(0xffffffffu, d0, 1);
                float e1 = __shfl_xor_sync(0xffffffffu, d1, 1);
                float e2 = __shfl_xor_sync(0xffffffffu, d2, 1);
                float e3 = __shfl_xor_sync(0xffffffffu, d3, 1);
                float iv = par ? e2 : d0;
                float fv = par ? e3 : d1;
                float gv = par ? d2 : e0;
                float ov = par ? d3 : e1;
                float cn = fmaf(fsig(fv), creg[mi][ni], fsig(iv) * ftanh(gv));
                creg[mi][ni] = cn;
                float hv = fsig(ov) * ftanh(cn);
                int hc = hcb + ni * 2;
                int row = rowb + mi * 16;
                if (hc < HH) {
                    hout[(size_t)row * KPAD + hc] = f2bf(hv);
                    if (last) g_hF[hc * NRP + row] = hv;
                }
            }
        }

        // slim row-group barrier: tid0-only fences, volatile spin (proven form);
        // prologue(t+1) prefetch overlaps the spin.
        __syncthreads();
        if (tid == 0) {
            __threadfence();
            atomicAdd(&g_bar2[rt][t], 1u);
        }
        if (t + 1 < TT) prologue(t + 1, dn);
        if (tid == 0) {
            while (*(volatile unsigned*)&g_bar2[rt][t] < 16u) {}
            __threadfence();
        }
        __syncthreads();
        #pragma unroll
        for (int mi = 0; mi < 2; mi++)
            #pragma unroll
            for (int ni = 0; ni < 4; ni++)
                #pragma unroll
                for (int q = 0; q < 4; q++) d[mi][ni][q] = dn[mi][ni][q];
    }
}

// ------------------------- h_last transpose -------------------------
__global__ void k_trh() {
    int idx = blockIdx.x * 256 + threadIdx.x;
    if (idx >= NR * HH) return;
    int n = idx / HH, k = idx % HH;
    g_hT[idx] = g_hF[k * NRP + n];
}

// ------------------------- tf32 MMA GEMM: C = act(A @ W + b) ----------------
__device__ __forceinline__ float* selbuf(int s) {
    switch (s) {
        case 0: return g_hT;
        case 1: return g_z1;
        case 2: return g_z2;
        default: return g_z3;
    }
}

__global__ __launch_bounds__(256) void k_gemmt(int aSel, const float* __restrict__ W,
                                               const float* __restrict__ bias, int cSel,
                                               int M, int K, int N, int doRelu) {
    const float* A = selbuf(aSel);
    float* C = selbuf(cSel);
    __shared__ __align__(16) float As[64 * 36];
    __shared__ __align__(16) float Ws[32 * 72];
    int tid  = threadIdx.x;
    int warp = tid >> 5;
    int lane = tid & 31;
    int g  = lane >> 2;
    int tg = lane & 3;
    int n0 = blockIdx.x * 64, m0 = blockIdx.y * 64;
    int wm = (warp >> 2) * 32;
    int wn = (warp & 3) * 16;

    int ami = tid >> 2;
    int akq = (tid & 3) * 8;
    int wkk = tid >> 3;
    int wnq = (tid & 7) * 8;

    float d[2][2][4];
    #pragma unroll
    for (int i = 0; i < 2; i++)
        #pragma unroll
        for (int j = 0; j < 2; j++)
            #pragma unroll
            for (int q = 0; q < 4; q++) d[i][j][q] = 0.f;

    int nslab = (K + 31) / 32;
    float rA[8], rW[8];

    {
        int m = m0 + ami;
        #pragma unroll
        for (int j = 0; j < 8; j++) {
            int k = akq + j;
            rA[j] = (m < M && k < K) ? A[(size_t)m * K + k] : 0.f;
        }
        #pragma unroll
        for (int j = 0; j < 8; j++) {
            int n = n0 + wnq + j;
            rW[j] = (wkk < K && n < N) ? W[(size_t)wkk * N + n] : 0.f;
        }
    }

    #pragma unroll 1
    for (int s = 0; s < nslab; s++) {
        #pragma unroll
        for (int j = 0; j < 8; j++) As[ami * 36 + akq + j] = tf32r(rA[j]);
        #pragma unroll
        for (int j = 0; j < 8; j++) Ws[wkk * 72 + wnq + j] = tf32r(rW[j]);
        __syncthreads();
        if (s + 1 < nslab) {
            int k0 = (s + 1) * 32;
            int m = m0 + ami;
            #pragma unroll
            for (int j = 0; j < 8; j++) {
                int k = k0 + akq + j;
                rA[j] = (m < M && k < K) ? A[(size_t)m * K + k] : 0.f;
            }
            #pragma unroll
            for (int j = 0; j < 8; j++) {
                int k = k0 + wkk;
                int n = n0 + wnq + j;
                rW[j] = (k < K && n < N) ? W[(size_t)k * N + n] : 0.f;
            }
        }
        const unsigned* Asu = reinterpret_cast<const unsigned*>(As);
        const unsigned* Wsu = reinterpret_cast<const unsigned*>(Ws);
        #pragma unroll
        for (int c8 = 0; c8 < 4; c8++) {
            int kc = c8 * 8;
            unsigned a[2][4], b[2][2];
            #pragma unroll
            for (int mi = 0; mi < 2; mi++) {
                int mbase = (wm + mi * 16 + g) * 36 + kc;
                a[mi][0] = Asu[mbase + tg];
                a[mi][1] = Asu[mbase + 8 * 36 + tg];
                a[mi][2] = Asu[mbase + tg + 4];
                a[mi][3] = Asu[mbase + 8 * 36 + tg + 4];
            }
            #pragma unroll
            for (int ni = 0; ni < 2; ni++) {
                int nb = wn + ni * 8 + g;
                b[ni][0] = Wsu[(kc + tg) * 72 + nb];
                b[ni][1] = Wsu[(kc + tg + 4) * 72 + nb];
            }
            #pragma unroll
            for (int mi = 0; mi < 2; mi++)
                #pragma unroll
                for (int ni = 0; ni < 2; ni++)
                    mma8(d[mi][ni], a[mi], b[ni]);
        }
        __syncthreads();
    }

    #pragma unroll
    for (int mi = 0; mi < 2; mi++) {
        #pragma unroll
        for (int ni = 0; ni < 2; ni++) {
            int mA = m0 + wm + mi * 16 + g;
            int mB = mA + 8;
            int n  = n0 + wn + ni * 8 + 2 * tg;
            float b0 = (n < N)     ? bias[n]     : 0.f;
            float b1 = (n + 1 < N) ? bias[n + 1] : 0.f;
            float v;
            if (mA < M) {
                if (n < N) {
                    v = d[mi][ni][0] + b0;
                    C[(size_t)mA * N + n] = doRelu ? fmaxf(v, 0.f) : v;
                }
                if (n + 1 < N) {
                    v = d[mi][ni][1] + b1;
                    C[(size_t)mA * N + n + 1] = doRelu ? fmaxf(v, 0.f) : v;
                }
            }
            if (mB < M) {
                if (n < N) {
                    v = d[mi][ni][2] + b0;
                    C[(size_t)mB * N + n] = doRelu ? fmaxf(v, 0.f) : v;
                }
                if (n + 1 < N) {
                    v = d[mi][ni][3] + b1;
                    C[(size_t)mB * N + n + 1] = doRelu ? fmaxf(v, 0.f) : v;
                }
            }
        }
    }
}

// ------------------------- final layer -------------------------
__global__ void k_final(const float* __restrict__ Wh4, const float* __restrict__ bh4,
                        float* __restrict__ out) {
    __shared__ float zs[M1];
    int n = blockIdx.x;
    int tid = threadIdx.x;
    for (int k = tid; k < M1; k += 256) zs[k] = g_z3[n * M1 + k];
    __syncthreads();
    int w = tid >> 5, lane = tid & 31;
    #pragma unroll
    for (int oi = 0; oi < 3; oi++) {
        int o = w + oi * 8;
        float p = 0.f;
        for (int k = lane; k < M1; k += 32) p = fmaf(zs[k], Wh4[k * OD + o], p);
        #pragma unroll
        for (int off = 16; off; off >>= 1) p += __shfl_down_sync(0xffffffffu, p, off);
        if (lane == 0) {
            float y = fsig(p + bh4[o]);
            int b = n / LL, l = n % LL;
            out[(b * OD + o) * LL + l] = y;
        }
    }
}

// ------------------------- launcher -------------------------
extern "C" void kernel_launch(void* const* d_in, const int* in_sizes, int n_in,
                              void* d_out, int out_size) {
    const float* x    = (const float*)d_in[0];
    const float* Ahat = (const float*)d_in[1];
    const float* W1   = (const float*)d_in[2];
    const float* W2   = (const float*)d_in[3];
    const float* W_ih = (const float*)d_in[4];
    const float* W_hh = (const float*)d_in[5];
    const float* b_ih = (const float*)d_in[6];
    const float* b_hh = (const float*)d_in[7];
    const float* Wh1  = (const float*)d_in[8];
    const float* bh1  = (const float*)d_in[9];
    const float* Wh2  = (const float*)d_in[10];
    const float* bh2  = (const float*)d_in[11];
    const float* Wh3  = (const float*)d_in[12];
    const float* bh3  = (const float*)d_in[13];
    const float* Wh4  = (const float*)d_in[14];
    const float* bh4  = (const float*)d_in[15];
    float* out = (float*)d_out;

    cudaFuncSetAttribute(k_lstm, cudaFuncAttributeMaxDynamicSharedMemorySize, SMEML);

    // launches 1-5 so that k_lstm is launch #6 (ncu -s 5 -c 1 target)
    k_trans<<<dim3(16, 127), dim3(32, 8)>>>(W_ih, W_hh, b_ih, b_hh, W1, W2);
    k_events<<<1, 512>>>();
    k_tables<<<8, 256>>>();
    k_front<<<BB * TT, 128>>>(x, Ahat);
    k_zero<<<512, 256>>>();
    k_lstm<<<dim3(16, 8), 256, SMEML>>>();

    k_trh<<<(NR * HH + 255) / 256, 256>>>();
    k_gemmt<<<dim3(47, 8), 256>>>(0, Wh1, bh1, 1, NR, HH, M1, 1);
    k_gemmt<<<dim3(16, 8), 256>>>(1, Wh2, bh2, 2, NR, M1, M2, 1);
    k_gemmt<<<dim3(47, 8), 256>>>(2, Wh3, bh3, 3, NR, M2, M1, 1);
    k_final<<<NR, 256>>>(Wh4, bh4, out);
}

// round 15
// speedup vs baseline: 1.9168x; 1.0206x over previous
#include <cuda_runtime.h>
#include <cuda_bf16.h>
#include <math.h>

#define BB 4
#define TT 192
#define LL 120
#define GG 500
#define HH 500      // HL
#define H4 2000
#define H4P 2048
#define KPAD 520    // padded K (bf16 units); 1040B row stride -> LDSM conflict-free
#define NR 480
#define NRP 512
#define OD 24
#define M1 3000
#define M2 1000

// k_lstm tiling: 128 blocks = 16 col-tiles(128 gate-cols) x 8 row-tiles(64 rows)
#define LSW (128 * KPAD * 2)    // 133120 W stripe bytes (resident)
#define LSA (64 * KPAD * 2)     // 66560 h stripe bytes
#define SMEML (LSW + LSA + 48)

// ------------------------- scratch (device globals) -------------------------
__device__ float g_Ppart[8][512];
__device__ float g_Npart[8][512];
__device__ float g_P[GG];
__device__ float g_Nv[GG];
__device__ float g_rho[GG];
__device__ float g_esign[GG];
__device__ int   g_ef[GG];
__device__ int   g_act0[GG];
__device__ int   g_nev[1];
__device__ __align__(16) float g_bias[H4P];                   // interleaved cq = hc*4+gate
__device__ __align__(16) float g_WihTp[GG * H4P];             // fp32 [f][cq]
__device__ __align__(16) float g_TAB[(GG + 1) * H4P * 2];     // [s][cq*2 + {A,B}]
__device__ __align__(16) unsigned short g_Whh[H4P * KPAD];    // bf16 W_hh [cq][k]
__device__ __align__(16) float4 g_uvs[TT * NRP];              // (u, v, seg-bits, 0)
__device__ __align__(16) unsigned short g_h3[3][NRP * KPAD];  // bf16 h ring [row][k]
__device__ unsigned g_bar2[8][TT];                            // per-row-group barriers
__device__ __align__(16) float g_hT[NR * HH];                 // fp32 h_last row-major
__device__ __align__(16) float g_z1[NR * M1];
__device__ __align__(16) float g_z2[NR * M2];
__device__ __align__(16) float g_z3[NR * M1];

// ------------------------- helpers -------------------------
__device__ __forceinline__ float fsig(float x) {
    return __fdividef(1.f, 1.f + __expf(-x));
}
__device__ __forceinline__ float ftanh(float x) {
    float ax = fabsf(x);
    float t  = __expf(-2.f * ax);
    float r  = __fdividef(1.f - t, 1.f + t);
    return copysignf(r, x);
}
__device__ __forceinline__ float tf32r(float x) {
    unsigned r;
    asm("cvt.rna.tf32.f32 %0, %1;" : "=r"(r) : "f"(x));
    return __uint_as_float(r);
}
__device__ __forceinline__ unsigned short f2bf(float v) {
    __nv_bfloat16 b = __float2bfloat16_rn(v);
    return *reinterpret_cast<unsigned short*>(&b);
}
__device__ __forceinline__ void mbar_init(unsigned a, unsigned c) {
    asm volatile("mbarrier.init.shared.b64 [%0], %1;" :: "r"(a), "r"(c) : "memory");
}
__device__ __forceinline__ void mbar_extx(unsigned a, unsigned tx) {
    asm volatile("mbarrier.arrive.expect_tx.shared.b64 _, [%0], %1;" :: "r"(a), "r"(tx) : "memory");
}
__device__ __forceinline__ void mbar_wait(unsigned a, unsigned ph) {
    asm volatile(
        "{\n\t.reg .pred P;\n"
        "W%=:\n\t"
        "mbarrier.try_wait.parity.acquire.cta.shared::cta.b64 P, [%0], %1, 0x989680;\n\t"
        "@P bra D%=;\n\t"
        "bra W%=;\n"
        "D%=:\n\t}"
        :: "r"(a), "r"(ph) : "memory");
}
__device__ __forceinline__ void bulkcp(unsigned dst, const void* src, unsigned bytes, unsigned mbar) {
    asm volatile(
        "cp.async.bulk.shared::cta.global.mbarrier::complete_tx::bytes [%0], [%1], %2, [%3];"
        :: "r"(dst), "l"(src), "r"(bytes), "r"(mbar) : "memory");
}
__device__ __forceinline__ void ldsm4(unsigned* r, unsigned addr) {
    asm volatile("ldmatrix.sync.aligned.m8n8.x4.shared.b16 {%0,%1,%2,%3}, [%4];"
                 : "=r"(r[0]), "=r"(r[1]), "=r"(r[2]), "=r"(r[3]) : "r"(addr));
}
__device__ __forceinline__ void mma16bf(float* d, const unsigned* a, const unsigned* b) {
    asm volatile(
        "mma.sync.aligned.m16n8k16.row.col.f32.bf16.bf16.f32 "
        "{%0,%1,%2,%3}, {%4,%5,%6,%7}, {%8,%9}, {%0,%1,%2,%3};"
        : "+f"(d[0]), "+f"(d[1]), "+f"(d[2]), "+f"(d[3])
        : "r"(a[0]), "r"(a[1]), "r"(a[2]), "r"(a[3]), "r"(b[0]), "r"(b[1]));
}
__device__ __forceinline__ void mma8(float* d, const unsigned* a, const unsigned* b) {
    asm volatile(
        "mma.sync.aligned.m16n8k8.row.col.f32.tf32.tf32.f32 "
        "{%0,%1,%2,%3}, {%4,%5,%6,%7}, {%8,%9}, {%0,%1,%2,%3};"
        : "+f"(d[0]), "+f"(d[1]), "+f"(d[2]), "+f"(d[3])
        : "r"(a[0]), "r"(a[1]), "r"(a[2]), "r"(a[3]), "r"(b[0]), "r"(b[1]));
}

// ------------------------- launch 1: weight reshuffles + bias + P,N partials
__global__ void k_trans(const float* __restrict__ W_ih, const float* __restrict__ W_hh,
                        const float* __restrict__ b_ih, const float* __restrict__ b_hh,
                        const float* __restrict__ W1, const float* __restrict__ b_W2) {
    __shared__ float tle[32][33];
    int x = threadIdx.x, y = threadIdx.y;
    if (blockIdx.y < 63) {
        int f0 = blockIdx.x * 32;
        int h0 = blockIdx.y * 32;
        for (int i = y; i < 32; i += 8) {
            int h = h0 + i, f = f0 + x;
            tle[i][x] = (h < H4 && f < GG) ? W_ih[(size_t)h * GG + f] : 0.f;
        }
        __syncthreads();
        for (int i = y; i < 32; i += 8) {
            int f = f0 + i, h = h0 + x;
            if (f < GG && h < H4) {
                int cq = (h % HH) * 4 + h / HH;
                g_WihTp[(size_t)f * H4P + cq] = tle[x][i];
            }
        }
    } else if (blockIdx.y < 126) {
        int r0 = (blockIdx.y - 63) * 32;
        int k0 = blockIdx.x * 32;
        for (int i = y; i < 32; i += 8) {
            int h = r0 + i;
            if (h < H4) {
                int cq = (h % HH) * 4 + h / HH;
                int k = k0 + x;
                g_Whh[(size_t)cq * KPAD + k] = (k < GG) ? f2bf(W_hh[(size_t)h * HH + k])
                                                        : (unsigned short)0;
            }
        }
        if (blockIdx.x == 0 && blockIdx.y == 125) {
            int tid = y * 32 + x;
            for (int h = tid; h < H4; h += 256) {
                int cq = (h % HH) * 4 + h / HH;
                g_bias[cq] = b_ih[h] + b_hh[h];
            }
        }
    } else {
        int tid = y * 32 + x;
        int part = blockIdx.x >> 1;
        int f = (blockIdx.x & 1) * 256 + tid;
        int g0 = part * 63;
        int g1 = min(g0 + 63, GG);
        float p = 0.f, n = 0.f;
        if (f < GG) {
            for (int g = g0; g < g1; g++) {
                float w = W1[g];
                float v = b_W2[(size_t)g * GG + f];
                p = fmaf(fmaxf(w, 0.f), v, p);
                n = fmaf(fmaxf(-w, 0.f), v, n);
            }
        }
        if (f < 512) {
            g_Ppart[part][f] = p;
            g_Npart[part][f] = n;
        }
    }
}

// ------------------------- launch 2: reduce P,N + breakpoint events ---------
__global__ void k_events() {
    __shared__ float srho[GG];
    __shared__ float ssg[GG];
    __shared__ int   sf[GG];
    __shared__ int   cnt;
    int tid = threadIdx.x;
    if (tid == 0) cnt = 0;
    float p = 0.f, n = 0.f;
    if (tid < GG) {
        #pragma unroll
        for (int part = 0; part < 8; part++) {
            p += g_Ppart[part][tid];
            n += g_Npart[part][tid];
        }
        g_P[tid]  = p;
        g_Nv[tid] = n;
    }
    __syncthreads();
    if (tid < GG) {
        int act0 = 0;
        float sgn = 0.f, rho = 0.f;
        if (n > 0.f) {
            if (p >= 0.f) { act0 = 1; }
            else { act0 = 0; rho = __fdividef(-p, n); sgn = 1.f; }
        } else if (n < 0.f) {
            if (p > 0.f) { act0 = 1; rho = __fdividef(p, -n); sgn = -1.f; }
            else { act0 = 0; }
        } else {
            act0 = (p > 0.f) ? 1 : 0;
        }
        g_act0[tid] = act0;
        if (sgn != 0.f) {
            int e = atomicAdd(&cnt, 1);
            srho[e] = rho; ssg[e] = sgn; sf[e] = tid;
        }
    }
    __syncthreads();
    int E = cnt;
    if (tid == 0) g_nev[0] = E;
    if (tid < E) {
        float r = srho[tid];
        int rank = 0;
        for (int j = 0; j < E; j++) {
            float rj = srho[j];
            rank += (rj < r) || (rj == r && j < tid);
        }
        g_rho[rank]   = r;
        g_esign[rank] = ssg[tid];
        g_ef[rank]    = sf[tid];
    }
}

// ------------------------- launch 3: interleaved segment tables -------------
__global__ void k_tables() {
    int cq = blockIdx.x * 256 + threadIdx.x;   // 0..2047
    float accA = 0.f, accB = 0.f;
    for (int f = 0; f < GG; f++) {
        if (g_act0[f]) {
            float w = g_WihTp[(size_t)f * H4P + cq];
            accA = fmaf(w, g_P[f],  accA);
            accB = fmaf(w, g_Nv[f], accB);
        }
    }
    g_TAB[(size_t)cq * 2]     = accA;
    g_TAB[(size_t)cq * 2 + 1] = accB;
    int E = g_nev[0];
    for (int e = 0; e < E; e++) {
        int f = g_ef[e];
        float w = g_WihTp[(size_t)f * H4P + cq] * g_esign[e];
        accA = fmaf(w, g_P[f],  accA);
        accB = fmaf(w, g_Nv[f], accB);
        size_t base = (size_t)(e + 1) * (H4P * 2) + (size_t)cq * 2;
        g_TAB[base]     = accA;
        g_TAB[base + 1] = accB;
    }
}

// ------------------------- launch 4: GCN front -> u,v,seg -------------------
__global__ void k_front(const float* __restrict__ x, const float* __restrict__ Ahat) {
    __shared__ float xr[LL], sp[LL], sn[LL];
    int bid = blockIdx.x;
    int b = bid / TT, t = bid % TT;
    int tid = threadIdx.x;
    if (tid < LL) xr[tid] = x[(b * TT + t) * LL + tid];
    __syncthreads();
    if (tid < LL) {
        float s = 0.f;
        for (int l = 0; l < LL; l++) s = fmaf(Ahat[l * LL + tid], xr[l], s);
        sp[tid] = fmaxf(s, 0.f);
        sn[tid] = fmaxf(-s, 0.f);
    }
    __syncthreads();
    if (tid < LL) {
        float uu = 0.f, vv = 0.f;
        for (int l = 0; l < LL; l++) {
            float a = Ahat[l * LL + tid];
            uu = fmaf(a, sp[l], uu);
            vv = fmaf(a, sn[l], vv);
        }
        int E = g_nev[0];
        int s;
        if (uu > 0.f) {
            float rho = vv / uu;
            int lo = 0, hi = E;
            while (lo < hi) {
                int mid = (lo + hi) >> 1;
                if (g_rho[mid] < rho) lo = mid + 1; else hi = mid;
            }
            s = lo;
        } else {
            s = (vv > 0.f) ? E : 0;
        }
        g_uvs[t * NRP + b * LL + tid] = make_float4(uu, vv, __int_as_float(s), 0.f);
    }
}

// ------------------------- launch 5: per-replay zero init -------------------
__global__ void k_zero() {
    const size_t H3W  = 3ull * NRP * KPAD / 2;              // u32 words of h ring
    const size_t BARW = 8 * TT;
    const size_t UVSW = (size_t)TT * (NRP - NR);            // pad float4 slots
    const size_t TOTAL = H3W + BARW + UVSW;
    size_t stride = (size_t)gridDim.x * 256;
    for (size_t i = (size_t)blockIdx.x * 256 + threadIdx.x; i < TOTAL; i += stride) {
        if (i < H3W) {
            reinterpret_cast<unsigned*>(g_h3)[i] = 0u;
        } else if (i < H3W + BARW) {
            (&g_bar2[0][0])[i - H3W] = 0u;
        } else {
            size_t j = i - H3W - BARW;
            size_t t = j / (NRP - NR);
            size_t r = NR + j % (NRP - NR);
            g_uvs[t * NRP + r] = make_float4(0.f, 0.f, 0.f, 0.f);
        }
    }
}

// ------------------------- launch 6: persistent LSTM ------------------------
// 128 blocks = 16 ct (128 gate-cols) x 8 rt (64 rows). W_hh stripe resident.
// Warp tile 32 cols x 32 rows. c in registers. Half-split h copy mbarriers.
__global__ __launch_bounds__(256) void k_lstm() {
    extern __shared__ __align__(16) char smc[];
    unsigned smb = (unsigned)__cvta_generic_to_shared(smc);
    unsigned sWb = smb, sAb = smb + LSW;
    unsigned mbH0 = smb + LSW + LSA;       // rows 0..31
    unsigned mbH1 = mbH0 + 8;              // rows 32..63
    unsigned mbW  = mbH0 + 16;
    int tid = threadIdx.x, warp = tid >> 5, lane = tid & 31;
    int g = lane >> 2, tg = lane & 3;
    int ct = blockIdx.x, rt = blockIdx.y;
    int R0 = rt * 64;
    int cwarp = warp & 3, rwarp = warp >> 2;
    int CW0 = ct * 128 + cwarp * 32;
    int RW0 = R0 + rwarp * 32;
    unsigned mbMine = rwarp ? mbH1 : mbH0;

    if (tid == 0) { mbar_init(mbH0, 1); mbar_init(mbH1, 1); mbar_init(mbW, 1); }
    __syncthreads();
    if (tid == 0) {
        mbar_extx(mbW, LSW);
        const char* wsrc = (const char*)(g_Whh + (size_t)ct * 128 * KPAD);
        bulkcp(sWb, wsrc, LSW / 2, mbW);
        bulkcp(sWb + LSW / 2, wsrc + LSW / 2, LSW / 2, mbW);
    }

    // ldsm addresses
    int arow = (lane & 7) + ((lane >> 3) & 1) * 8;
    unsigned akB = ((lane >> 4) & 1) * 16;
    unsigned aAdr[2];
    #pragma unroll
    for (int mi = 0; mi < 2; mi++)
        aAdr[mi] = sAb + (unsigned)((rwarp * 32 + mi * 16 + arow) * (KPAD * 2)) + akB;
    int wn0 = cwarp * 32 + (lane & 7) + ((lane >> 4) & 1) * 8;
    unsigned wkB = ((lane >> 3) & 1) * 16;
    unsigned wAdr0 = sWb + (unsigned)(wn0 * (KPAD * 2)) + wkB;
    unsigned wAdr1 = wAdr0 + 16u * (KPAD * 2);

    int cA0 = CW0 + 2 * tg;
    float2 bi[4];
    #pragma unroll
    for (int ni = 0; ni < 4; ni++) bi[ni] = *(const float2*)&g_bias[cA0 + ni * 8];

    // persistent c registers + epilogue coordinates
    float creg[2][4];
    #pragma unroll
    for (int mi = 0; mi < 2; mi++)
        #pragma unroll
        for (int ni = 0; ni < 4; ni++) creg[mi][ni] = 0.f;
    int par = lane & 1;
    int hcb = (CW0 >> 2) + (tg >> 1);
    int rowb = RW0 + g + par * 8;

    float d[2][4][4], dn[2][4][4];

    auto prologue = [&](int t, float (&dd)[2][4][4]) {
        #pragma unroll
        for (int mi = 0; mi < 2; mi++) {
            int rA = RW0 + mi * 16 + g;
            float4 pa = g_uvs[t * NRP + rA];
            float4 pb = g_uvs[t * NRP + rA + 8];
            const float4* TA = (const float4*)&g_TAB[(size_t)__float_as_int(pa.z) * (H4P * 2)];
            const float4* TB = (const float4*)&g_TAB[(size_t)__float_as_int(pb.z) * (H4P * 2)];
            #pragma unroll
            for (int ni = 0; ni < 4; ni++) {
                int c = cA0 + ni * 8;
                float4 qa = TA[c >> 1];
                float4 qb = TB[c >> 1];
                dd[mi][ni][0] = fmaf(pa.x, qa.x, fmaf(pa.y, qa.y, bi[ni].x));
                dd[mi][ni][1] = fmaf(pa.x, qa.z, fmaf(pa.y, qa.w, bi[ni].y));
                dd[mi][ni][2] = fmaf(pb.x, qb.x, fmaf(pb.y, qb.y, bi[ni].x));
                dd[mi][ni][3] = fmaf(pb.x, qb.z, fmaf(pb.y, qb.w, bi[ni].y));
            }
        }
    };

    prologue(0, d);
    mbar_wait(mbW, 0);

    #pragma unroll 1
    for (int t = 0; t < TT; t++) {
        const unsigned short* hin = g_h3[(t + 2) % 3];
        unsigned short* hout = g_h3[t % 3];
        if (tid == 0) {
            const char* src = (const char*)(hin + (size_t)R0 * KPAD);
            mbar_extx(mbH0, LSA / 2);
            bulkcp(sAb, src, LSA / 2, mbH0);
            mbar_extx(mbH1, LSA / 2);
            bulkcp(sAb + LSA / 2, src + LSA / 2, LSA / 2, mbH1);
        }
        mbar_wait(mbMine, t & 1);   // each warp waits only for its row half

        #pragma unroll 4
        for (int c16 = 0; c16 < 32; c16++) {
            unsigned kB = (unsigned)(c16 * 32);
            unsigned b8[8], a[2][4];
            ldsm4(b8,     wAdr0 + kB);
            ldsm4(b8 + 4, wAdr1 + kB);
            ldsm4(a[0], aAdr[0] + kB);
            ldsm4(a[1], aAdr[1] + kB);
            #pragma unroll
            for (int mi = 0; mi < 2; mi++) {
                mma16bf(d[mi][0], a[mi], b8);
                mma16bf(d[mi][1], a[mi], b8 + 2);
                mma16bf(d[mi][2], a[mi], b8 + 4);
                mma16bf(d[mi][3], a[mi], b8 + 6);
            }
        }

        // epilogue: lane-split (even lane -> row rA, odd lane -> row rB)
        int last = (t == TT - 1);
        #pragma unroll
        for (int mi = 0; mi < 2; mi++) {
            #pragma unroll
            for (int ni = 0; ni < 4; ni++) {
                float d0 = d[mi][ni][0], d1 = d[mi][ni][1];
                float d2 = d[mi][ni][2], d3 = d[mi][ni][3];
                float e0 = __shfl_xor_sync(0xffffffffu, d0, 1);
                float e1 = __shfl_xor_sync(0xffffffffu, d1, 1);
                float e2 = __shfl_xor_sync(0xffffffffu, d2, 1);
                float e3 = __shfl_xor_sync(0xffffffffu, d3, 1);
                float iv = par ? e2 : d0;
                float fv = par ? e3 : d1;
                float gv = par ? d2 : e0;
                float ov = par ? d3 : e1;
                float cn = fmaf(fsig(fv), creg[mi][ni], fsig(iv) * ftanh(gv));
                creg[mi][ni] = cn;
                float hv = fsig(ov) * ftanh(cn);
                int hc = hcb + ni * 2;
                int row = rowb + mi * 16;
                if (hc < HH) {
                    hout[(size_t)row * KPAD + hc] = f2bf(hv);
                    if (last && row < NR) g_hT[(size_t)row * HH + hc] = hv;
                }
            }
        }

        // slim row-group barrier: tid0-only fences, volatile spin;
        // prologue(t+1) prefetch overlaps the spin.
        __syncthreads();
        if (tid == 0) {
            __threadfence();
            atomicAdd(&g_bar2[rt][t], 1u);
        }
        if (t + 1 < TT) prologue(t + 1, dn);
        if (tid == 0) {
            while (*(volatile unsigned*)&g_bar2[rt][t] < 16u) {}
            __threadfence();
        }
        __syncthreads();
        #pragma unroll
        for (int mi = 0; mi < 2; mi++)
            #pragma unroll
            for (int ni = 0; ni < 4; ni++)
                #pragma unroll
                for (int q = 0; q < 4; q++) d[mi][ni][q] = dn[mi][ni][q];
    }
}

// ------------------------- tf32 MMA GEMM: C = act(A @ W + b) ----------------
__device__ __forceinline__ float* selbuf(int s) {
    switch (s) {
        case 0: return g_hT;
        case 1: return g_z1;
        case 2: return g_z2;
        default: return g_z3;
    }
}

__global__ __launch_bounds__(256) void k_gemmt(int aSel, const float* __restrict__ W,
                                               const float* __restrict__ bias, int cSel,
                                               int M, int K, int N, int doRelu) {
    const float* A = selbuf(aSel);
    float* C = selbuf(cSel);
    __shared__ __align__(16) float As[64 * 36];
    __shared__ __align__(16) float Ws[32 * 72];
    int tid  = threadIdx.x;
    int warp = tid >> 5;
    int lane = tid & 31;
    int g  = lane >> 2;
    int tg = lane & 3;
    int n0 = blockIdx.x * 64, m0 = blockIdx.y * 64;
    int wm = (warp >> 2) * 32;
    int wn = (warp & 3) * 16;

    int ami = tid >> 2;
    int akq = (tid & 3) * 8;
    int wkk = tid >> 3;
    int wnq = (tid & 7) * 8;

    float d[2][2][4];
    #pragma unroll
    for (int i = 0; i < 2; i++)
        #pragma unroll
        for (int j = 0; j < 2; j++)
            #pragma unroll
            for (int q = 0; q < 4; q++) d[i][j][q] = 0.f;

    int nslab = (K + 31) / 32;
    float rA[8], rW[8];

    {
        int m = m0 + ami;
        #pragma unroll
        for (int j = 0; j < 8; j++) {
            int k = akq + j;
            rA[j] = (m < M && k < K) ? A[(size_t)m * K + k] : 0.f;
        }
        #pragma unroll
        for (int j = 0; j < 8; j++) {
            int n = n0 + wnq + j;
            rW[j] = (wkk < K && n < N) ? W[(size_t)wkk * N + n] : 0.f;
        }
    }

    #pragma unroll 1
    for (int s = 0; s < nslab; s++) {
        #pragma unroll
        for (int j = 0; j < 8; j++) As[ami * 36 + akq + j] = tf32r(rA[j]);
        #pragma unroll
        for (int j = 0; j < 8; j++) Ws[wkk * 72 + wnq + j] = tf32r(rW[j]);
        __syncthreads();
        if (s + 1 < nslab) {
            int k0 = (s + 1) * 32;
            int m = m0 + ami;
            #pragma unroll
            for (int j = 0; j < 8; j++) {
                int k = k0 + akq + j;
                rA[j] = (m < M && k < K) ? A[(size_t)m * K + k] : 0.f;
            }
            #pragma unroll
            for (int j = 0; j < 8; j++) {
                int k = k0 + wkk;
                int n = n0 + wnq + j;
                rW[j] = (k < K && n < N) ? W[(size_t)k * N + n] : 0.f;
            }
        }
        const unsigned* Asu = reinterpret_cast<const unsigned*>(As);
        const unsigned* Wsu = reinterpret_cast<const unsigned*>(Ws);
        #pragma unroll
        for (int c8 = 0; c8 < 4; c8++) {
            int kc = c8 * 8;
            unsigned a[2][4], b[2][2];
            #pragma unroll
            for (int mi = 0; mi < 2; mi++) {
                int mbase = (wm + mi * 16 + g) * 36 + kc;
                a[mi][0] = Asu[mbase + tg];
                a[mi][1] = Asu[mbase + 8 * 36 + tg];
                a[mi][2] = Asu[mbase + tg + 4];
                a[mi][3] = Asu[mbase + 8 * 36 + tg + 4];
            }
            #pragma unroll
            for (int ni = 0; ni < 2; ni++) {
                int nb = wn + ni * 8 + g;
                b[ni][0] = Wsu[(kc + tg) * 72 + nb];
                b[ni][1] = Wsu[(kc + tg + 4) * 72 + nb];
            }
            #pragma unroll
            for (int mi = 0; mi < 2; mi++)
                #pragma unroll
                for (int ni = 0; ni < 2; ni++)
                    mma8(d[mi][ni], a[mi], b[ni]);
        }
        __syncthreads();
    }

    #pragma unroll
    for (int mi = 0; mi < 2; mi++) {
        #pragma unroll
        for (int ni = 0; ni < 2; ni++) {
            int mA = m0 + wm + mi * 16 + g;
            int mB = mA + 8;
            int n  = n0 + wn + ni * 8 + 2 * tg;
            float b0 = (n < N)     ? bias[n]     : 0.f;
            float b1 = (n + 1 < N) ? bias[n + 1] : 0.f;
            float v;
            if (mA < M) {
                if (n < N) {
                    v = d[mi][ni][0] + b0;
                    C[(size_t)mA * N + n] = doRelu ? fmaxf(v, 0.f) : v;
                }
                if (n + 1 < N) {
                    v = d[mi][ni][1] + b1;
                    C[(size_t)mA * N + n + 1] = doRelu ? fmaxf(v, 0.f) : v;
                }
            }
            if (mB < M) {
                if (n < N) {
                    v = d[mi][ni][2] + b0;
                    C[(size_t)mB * N + n] = doRelu ? fmaxf(v, 0.f) : v;
                }
                if (n + 1 < N) {
                    v = d[mi][ni][3] + b1;
                    C[(size_t)mB * N + n + 1] = doRelu ? fmaxf(v, 0.f) : v;
                }
            }
        }
    }
}

// ------------------------- final layer -------------------------
__global__ void k_final(const float* __restrict__ Wh4, const float* __restrict__ bh4,
                        float* __restrict__ out) {
    __shared__ float zs[M1];
    int n = blockIdx.x;
    int tid = threadIdx.x;
    for (int k = tid; k < M1; k += 256) zs[k] = g_z3[n * M1 + k];
    __syncthreads();
    int w = tid >> 5, lane = tid & 31;
    #pragma unroll
    for (int oi = 0; oi < 3; oi++) {
        int o = w + oi * 8;
        float p = 0.f;
        for (int k = lane; k < M1; k += 32) p = fmaf(zs[k], Wh4[k * OD + o], p);
        #pragma unroll
        for (int off = 16; off; off >>= 1) p += __shfl_down_sync(0xffffffffu, p, off);
        if (lane == 0) {
            float y = fsig(p + bh4[o]);
            int b = n / LL, l = n % LL;
            out[(b * OD + o) * LL + l] = y;
        }
    }
}

// ------------------------- launcher -------------------------
extern "C" void kernel_launch(void* const* d_in, const int* in_sizes, int n_in,
                              void* d_out, int out_size) {
    const float* x    = (const float*)d_in[0];
    const float* Ahat = (const float*)d_in[1];
    const float* W1   = (const float*)d_in[2];
    const float* W2   = (const float*)d_in[3];
    const float* W_ih = (const float*)d_in[4];
    const float* W_hh = (const float*)d_in[5];
    const float* b_ih = (const float*)d_in[6];
    const float* b_hh = (const float*)d_in[7];
    const float* Wh1  = (const float*)d_in[8];
    const float* bh1  = (const float*)d_in[9];
    const float* Wh2  = (const float*)d_in[10];
    const float* bh2  = (const float*)d_in[11];
    const float* Wh3  = (const float*)d_in[12];
    const float* bh3  = (const float*)d_in[13];
    const float* Wh4  = (const float*)d_in[14];
    const float* bh4  = (const float*)d_in[15];
    float* out = (float*)d_out;

    cudaFuncSetAttribute(k_lstm, cudaFuncAttributeMaxDynamicSharedMemorySize, SMEML);

    // launches 1-5 so that k_lstm is launch #6 (ncu -s 5 -c 1 target)
    k_trans<<<dim3(16, 127), dim3(32, 8)>>>(W_ih, W_hh, b_ih, b_hh, W1, W2);
    k_events<<<1, 512>>>();
    k_tables<<<8, 256>>>();
    k_front<<<BB * TT, 128>>>(x, Ahat);
    k_zero<<<512, 256>>>();
    k_lstm<<<dim3(16, 8), 256, SMEML>>>();

    k_gemmt<<<dim3(47, 8), 256>>>(0, Wh1, bh1, 1, NR, HH, M1, 1);
    k_gemmt<<<dim3(16, 8), 256>>>(1, Wh2, bh2, 2, NR, M1, M2, 1);
    k_gemmt<<<dim3(47, 8), 256>>>(2, Wh3, bh3, 3, NR, M2, M1, 1);
    k_final<<<NR, 256>>>(Wh4, bh4, out);
}